// round 1
// baseline (speedup 1.0000x reference)
#include <cuda_runtime.h>
#include <cstdint>
#include <cstddef>

#define D_MODEL 512
#define NHEADS  8
#define DEPTH   64
#define BATCH   2
#define SEQ     2048
#define MROWS   (BATCH*SEQ)   // 4096

#define LOG2E 1.4426950408889634f
#define QSTRIDE 68            // padded smem row stride (floats), %4==0, kills stride-64 conflicts

// scratch (allocation-free rule: __device__ globals)
__device__ float g_q[MROWS * D_MODEL];
__device__ float g_k[MROWS * D_MODEL];
__device__ float g_v[MROWS * D_MODEL];
__device__ float g_att[MROWS * D_MODEL];

__device__ __forceinline__ float fast_ex2(float x) {
    float y;
    asm("ex2.approx.ftz.f32 %0, %1;" : "=f"(y) : "f"(x));
    return y;
}

// ---------------------------------------------------------------------------
// GEMM: out[m,n] = (sum_k A[m,k]*W[n,k] + bias[n]) * alpha
// A: [MROWS, 512] row-major, W: [512, 512] row-major (K contiguous for both).
// 128x128x8 tile, 256 threads, 8x8 per thread.
// ---------------------------------------------------------------------------
__global__ __launch_bounds__(256) void gemm_bias(
    const float* __restrict__ A, const float* __restrict__ W,
    const float* __restrict__ bias, float* __restrict__ out, float alpha)
{
    __shared__ float As[8][128];
    __shared__ float Bs[8][128];

    const int tid = threadIdx.x;
    const int m0 = blockIdx.y * 128;
    const int n0 = blockIdx.x * 128;
    const int tx = tid & 15;        // 0..15  (n sub-tile)
    const int ty = tid >> 4;        // 0..15  (m sub-tile)
    const int lrow = tid >> 1;      // 0..127 (load row)
    const int lcol = (tid & 1) << 2;// 0 or 4 (load k offset)

    float acc[8][8];
    #pragma unroll
    for (int i = 0; i < 8; i++)
        #pragma unroll
        for (int j = 0; j < 8; j++) acc[i][j] = 0.f;

    const float* Aptr = A + (size_t)(m0 + lrow) * D_MODEL + lcol;
    const float* Wptr = W + (size_t)(n0 + lrow) * D_MODEL + lcol;

    for (int k0 = 0; k0 < D_MODEL; k0 += 8) {
        float4 a4 = *(const float4*)(Aptr + k0);
        float4 b4 = *(const float4*)(Wptr + k0);
        __syncthreads();
        As[lcol + 0][lrow] = a4.x; As[lcol + 1][lrow] = a4.y;
        As[lcol + 2][lrow] = a4.z; As[lcol + 3][lrow] = a4.w;
        Bs[lcol + 0][lrow] = b4.x; Bs[lcol + 1][lrow] = b4.y;
        Bs[lcol + 2][lrow] = b4.z; Bs[lcol + 3][lrow] = b4.w;
        __syncthreads();
        #pragma unroll
        for (int k = 0; k < 8; k++) {
            float4 a0 = *(const float4*)&As[k][ty * 8];
            float4 a1 = *(const float4*)&As[k][ty * 8 + 4];
            float4 b0 = *(const float4*)&Bs[k][tx * 8];
            float4 b1 = *(const float4*)&Bs[k][tx * 8 + 4];
            float af[8] = {a0.x, a0.y, a0.z, a0.w, a1.x, a1.y, a1.z, a1.w};
            float bf[8] = {b0.x, b0.y, b0.z, b0.w, b1.x, b1.y, b1.z, b1.w};
            #pragma unroll
            for (int i = 0; i < 8; i++)
                #pragma unroll
                for (int j = 0; j < 8; j++)
                    acc[i][j] += af[i] * bf[j];
        }
    }

    #pragma unroll
    for (int i = 0; i < 8; i++) {
        const size_t orow = (size_t)(m0 + ty * 8 + i) * D_MODEL;
        #pragma unroll
        for (int j = 0; j < 8; j += 4) {
            int n = n0 + tx * 8 + j;
            float4 o;
            o.x = (acc[i][j + 0] + bias[n + 0]) * alpha;
            o.y = (acc[i][j + 1] + bias[n + 1]) * alpha;
            o.z = (acc[i][j + 2] + bias[n + 2]) * alpha;
            o.w = (acc[i][j + 3] + bias[n + 3]) * alpha;
            *(float4*)&out[orow + n] = o;
        }
    }
}

// ---------------------------------------------------------------------------
// Flash attention, fp32. Grid: (SEQ/64, BATCH*NHEADS), 128 threads.
// Block handles 64 query rows of one (b,h). Q scaled by (1/8)*log2e upstream,
// so softmax is exp2-based.
// Thread tile: 4 q-rows (trow=tid>>3) x 8 kv-cols / d-cols (tcol=tid&7).
// Row reductions across the 8 lanes sharing a row via shfl.xor {1,2,4}.
// P is staged through smem, aliasing the dead K buffer.
// ---------------------------------------------------------------------------
__global__ __launch_bounds__(128) void attn_kernel(
    const float* __restrict__ Q, const float* __restrict__ K,
    const float* __restrict__ V, float* __restrict__ Oout)
{
    extern __shared__ float sm[];
    float (*Qs)[QSTRIDE] = (float (*)[QSTRIDE])sm;
    float (*Ks)[QSTRIDE] = (float (*)[QSTRIDE])(sm + 64 * QSTRIDE);
    float (*Vs)[QSTRIDE] = (float (*)[QSTRIDE])(sm + 2 * 64 * QSTRIDE);

    const int tid = threadIdx.x;
    const int bh = blockIdx.y;        // 0..15
    const int b = bh >> 3, h = bh & 7;
    const int row0 = blockIdx.x * 64;
    const size_t headoff = (size_t)h * DEPTH;
    const size_t qbase  = ((size_t)(b * SEQ + row0)) * D_MODEL + headoff;
    const size_t kvbase = ((size_t)(b * SEQ)) * D_MODEL + headoff;

    // load Q tile [64 x 64]
    #pragma unroll
    for (int i = 0; i < 8; i++) {
        int lin = tid + i * 128;       // float4 index, 0..1023
        int r = lin >> 4;
        int c = (lin & 15) << 2;
        *(float4*)&Qs[r][c] = *(const float4*)&Q[qbase + (size_t)r * D_MODEL + c];
    }

    const int trow = tid >> 3;   // 0..15
    const int tcol = tid & 7;    // 0..7

    float mrow[4], lsum[4], O[4][8];
    #pragma unroll
    for (int r = 0; r < 4; r++) {
        mrow[r] = -3.0e38f;
        lsum[r] = 0.f;
        #pragma unroll
        for (int d = 0; d < 8; d++) O[r][d] = 0.f;
    }

    for (int t = 0; t < SEQ; t += 64) {
        __syncthreads();   // everyone done reading P(smem=Ks) / Vs of prev iter
        #pragma unroll
        for (int i = 0; i < 8; i++) {
            int lin = tid + i * 128;
            int r = lin >> 4;
            int c = (lin & 15) << 2;
            size_t g = kvbase + (size_t)(t + r) * D_MODEL + c;
            *(float4*)&Ks[r][c] = *(const float4*)&K[g];
            *(float4*)&Vs[r][c] = *(const float4*)&V[g];
        }
        __syncthreads();   // tiles (and Q on iter 0) visible

        // ---- S = Q * K^T  (4x8 per thread) ----
        float s[4][8];
        #pragma unroll
        for (int r = 0; r < 4; r++)
            #pragma unroll
            for (int c = 0; c < 8; c++) s[r][c] = 0.f;

        #pragma unroll
        for (int kk = 0; kk < DEPTH; kk += 4) {
            float4 q4[4];
            #pragma unroll
            for (int r = 0; r < 4; r++)
                q4[r] = *(const float4*)&Qs[trow * 4 + r][kk];
            #pragma unroll
            for (int c = 0; c < 8; c++) {
                float4 k4 = *(const float4*)&Ks[tcol * 8 + c][kk];
                #pragma unroll
                for (int r = 0; r < 4; r++) {
                    s[r][c] += q4[r].x * k4.x;
                    s[r][c] += q4[r].y * k4.y;
                    s[r][c] += q4[r].z * k4.z;
                    s[r][c] += q4[r].w * k4.w;
                }
            }
        }

        // ---- online softmax (log2 domain) ----
        #pragma unroll
        for (int r = 0; r < 4; r++) {
            float mx = s[r][0];
            #pragma unroll
            for (int c = 1; c < 8; c++) mx = fmaxf(mx, s[r][c]);
            mx = fmaxf(mx, __shfl_xor_sync(0xffffffffu, mx, 1));
            mx = fmaxf(mx, __shfl_xor_sync(0xffffffffu, mx, 2));
            mx = fmaxf(mx, __shfl_xor_sync(0xffffffffu, mx, 4));
            float mnew = fmaxf(mrow[r], mx);
            float corr = fast_ex2(mrow[r] - mnew);
            mrow[r] = mnew;
            float ls = 0.f;
            #pragma unroll
            for (int c = 0; c < 8; c++) {
                float p = fast_ex2(s[r][c] - mnew);
                s[r][c] = p;
                ls += p;
            }
            ls += __shfl_xor_sync(0xffffffffu, ls, 1);
            ls += __shfl_xor_sync(0xffffffffu, ls, 2);
            ls += __shfl_xor_sync(0xffffffffu, ls, 4);
            lsum[r] = lsum[r] * corr + ls;
            #pragma unroll
            for (int d = 0; d < 8; d++) O[r][d] *= corr;
        }

        __syncthreads();   // done reading K; Ks buffer now becomes P
        #pragma unroll
        for (int r = 0; r < 4; r++) {
            *(float4*)&Ks[trow * 4 + r][tcol * 8]     =
                make_float4(s[r][0], s[r][1], s[r][2], s[r][3]);
            *(float4*)&Ks[trow * 4 + r][tcol * 8 + 4] =
                make_float4(s[r][4], s[r][5], s[r][6], s[r][7]);
        }
        __syncthreads();   // P visible

        // ---- O += P * V ----
        #pragma unroll 8
        for (int c = 0; c < 64; c++) {
            float4 va = *(const float4*)&Vs[c][tcol * 8];
            float4 vb = *(const float4*)&Vs[c][tcol * 8 + 4];
            #pragma unroll
            for (int r = 0; r < 4; r++) {
                float p = Ks[trow * 4 + r][c];
                O[r][0] += p * va.x; O[r][1] += p * va.y;
                O[r][2] += p * va.z; O[r][3] += p * va.w;
                O[r][4] += p * vb.x; O[r][5] += p * vb.y;
                O[r][6] += p * vb.z; O[r][7] += p * vb.w;
            }
        }
    }

    // ---- normalize + write [B,S,D] layout (head h occupies cols h*64..) ----
    #pragma unroll
    for (int r = 0; r < 4; r++) {
        float inv = 1.f / lsum[r];
        size_t addr = ((size_t)(b * SEQ + row0 + trow * 4 + r)) * D_MODEL
                    + headoff + tcol * 8;
        *(float4*)&Oout[addr] =
            make_float4(O[r][0] * inv, O[r][1] * inv, O[r][2] * inv, O[r][3] * inv);
        *(float4*)&Oout[addr + 4] =
            make_float4(O[r][4] * inv, O[r][5] * inv, O[r][6] * inv, O[r][7] * inv);
    }
}

// ---------------------------------------------------------------------------
extern "C" void kernel_launch(void* const* d_in, const int* in_sizes, int n_in,
                              void* d_out, int out_size)
{
    const float* x  = (const float*)d_in[0];
    const float* Wq = (const float*)d_in[1];
    const float* bq = (const float*)d_in[2];
    const float* Wk = (const float*)d_in[3];
    const float* bk = (const float*)d_in[4];
    const float* Wv = (const float*)d_in[5];
    const float* bv = (const float*)d_in[6];
    const float* Wo = (const float*)d_in[7];
    const float* bo = (const float*)d_in[8];
    float* out = (float*)d_out;

    float *q, *k, *v, *att;
    cudaGetSymbolAddress((void**)&q,   g_q);
    cudaGetSymbolAddress((void**)&k,   g_k);
    cudaGetSymbolAddress((void**)&v,   g_v);
    cudaGetSymbolAddress((void**)&att, g_att);

    dim3 pgrid(D_MODEL / 128, MROWS / 128);   // (4, 32)

    // Q projection: fold 1/sqrt(depth) AND log2(e) so attention works in exp2 domain
    gemm_bias<<<pgrid, 256>>>(x, Wq, bq, q, 0.125f * LOG2E);
    gemm_bias<<<pgrid, 256>>>(x, Wk, bk, k, 1.0f);
    gemm_bias<<<pgrid, 256>>>(x, Wv, bv, v, 1.0f);

    const int smem_bytes = 3 * 64 * QSTRIDE * (int)sizeof(float); // 52224
    cudaFuncSetAttribute(attn_kernel,
                         cudaFuncAttributeMaxDynamicSharedMemorySize, smem_bytes);
    attn_kernel<<<dim3(SEQ / 64, BATCH * NHEADS), 128, smem_bytes>>>(q, k, v, att);

    gemm_bias<<<pgrid, 256>>>(att, Wo, bo, out, 1.0f);
}

// round 2
// speedup vs baseline: 2.3894x; 2.3894x over previous
#include <cuda_runtime.h>
#include <cstdint>
#include <cstddef>

#define D_MODEL 512
#define NHEADS  8
#define DEPTH   64
#define BATCH   2
#define SEQ     2048
#define MROWS   (BATCH*SEQ)   // 4096

#define LOG2E 1.4426950408889634f
#define QSTRIDE 68            // padded smem row stride (floats)

// attention tiling
#define QROWS 128             // q rows per block
#define KTILE 64              // kv rows per tile

// scratch (allocation-free rule: __device__ globals)
__device__ float g_q[MROWS * D_MODEL];
__device__ float g_k[MROWS * D_MODEL];
__device__ float g_v[MROWS * D_MODEL];
__device__ float g_att[MROWS * D_MODEL];

__device__ __forceinline__ float fast_ex2(float x) {
    float y;
    asm("ex2.approx.ftz.f32 %0, %1;" : "=f"(y) : "f"(x));
    return y;
}

// ---------------------------------------------------------------------------
// GEMM: out[m,n] = (sum_k A[m,k]*W[n,k] + bias[n]) * alpha
// A: [MROWS, 512] row-major, W: [512, 512] row-major (K contiguous for both).
// 128x128x8 tile, 256 threads, 8x8 per thread.
// ---------------------------------------------------------------------------
__global__ __launch_bounds__(256) void gemm_bias(
    const float* __restrict__ A, const float* __restrict__ W,
    const float* __restrict__ bias, float* __restrict__ out, float alpha)
{
    __shared__ float As[8][128];
    __shared__ float Bs[8][128];

    const int tid = threadIdx.x;
    const int m0 = blockIdx.y * 128;
    const int n0 = blockIdx.x * 128;
    const int tx = tid & 15;        // 0..15  (n sub-tile)
    const int ty = tid >> 4;        // 0..15  (m sub-tile)
    const int lrow = tid >> 1;      // 0..127 (load row)
    const int lcol = (tid & 1) << 2;// 0 or 4 (load k offset)

    float acc[8][8];
    #pragma unroll
    for (int i = 0; i < 8; i++)
        #pragma unroll
        for (int j = 0; j < 8; j++) acc[i][j] = 0.f;

    const float* Aptr = A + (size_t)(m0 + lrow) * D_MODEL + lcol;
    const float* Wptr = W + (size_t)(n0 + lrow) * D_MODEL + lcol;

    for (int k0 = 0; k0 < D_MODEL; k0 += 8) {
        float4 a4 = *(const float4*)(Aptr + k0);
        float4 b4 = *(const float4*)(Wptr + k0);
        __syncthreads();
        As[lcol + 0][lrow] = a4.x; As[lcol + 1][lrow] = a4.y;
        As[lcol + 2][lrow] = a4.z; As[lcol + 3][lrow] = a4.w;
        Bs[lcol + 0][lrow] = b4.x; Bs[lcol + 1][lrow] = b4.y;
        Bs[lcol + 2][lrow] = b4.z; Bs[lcol + 3][lrow] = b4.w;
        __syncthreads();
        #pragma unroll
        for (int k = 0; k < 8; k++) {
            float4 a0 = *(const float4*)&As[k][ty * 8];
            float4 a1 = *(const float4*)&As[k][ty * 8 + 4];
            float4 b0 = *(const float4*)&Bs[k][tx * 8];
            float4 b1 = *(const float4*)&Bs[k][tx * 8 + 4];
            float af[8] = {a0.x, a0.y, a0.z, a0.w, a1.x, a1.y, a1.z, a1.w};
            float bf[8] = {b0.x, b0.y, b0.z, b0.w, b1.x, b1.y, b1.z, b1.w};
            #pragma unroll
            for (int i = 0; i < 8; i++)
                #pragma unroll
                for (int j = 0; j < 8; j++)
                    acc[i][j] += af[i] * bf[j];
        }
    }

    #pragma unroll
    for (int i = 0; i < 8; i++) {
        const size_t orow = (size_t)(m0 + ty * 8 + i) * D_MODEL;
        #pragma unroll
        for (int j = 0; j < 8; j += 4) {
            int n = n0 + tx * 8 + j;
            float4 o;
            o.x = (acc[i][j + 0] + bias[n + 0]) * alpha;
            o.y = (acc[i][j + 1] + bias[n + 1]) * alpha;
            o.z = (acc[i][j + 2] + bias[n + 2]) * alpha;
            o.w = (acc[i][j + 3] + bias[n + 3]) * alpha;
            *(float4*)&out[orow + n] = o;
        }
    }
}

// ---------------------------------------------------------------------------
// Flash attention, fp32, 8x8 per-thread tiles (crossbar-balanced: 0.25 fl/FMA).
// Grid: (SEQ/128, BATCH*NHEADS), 128 threads.
// Block handles 128 query rows of one (b,h); kv tile = 64 rows.
// Thread layout: tcol = tid&7, trow = tid>>3.
//   q rows   : trow + 16*i   (i=0..7, interleaved -> conflict-free)
//   kv cols  : tcol + 8*j    (j=0..7, interleaved -> conflict-free K loads)
//   d cols   : tcol*8 .. +8  (contiguous -> float4 V loads / O stores)
// P staged in a dedicated smem buffer.
// Q pre-scaled by (1/8)*log2e so softmax uses ex2.approx.
// ---------------------------------------------------------------------------
__global__ __launch_bounds__(128) void attn_kernel(
    const float* __restrict__ Q, const float* __restrict__ K,
    const float* __restrict__ V, float* __restrict__ Oout)
{
    extern __shared__ float sm[];
    float (*Qs)[QSTRIDE] = (float (*)[QSTRIDE])sm;                        // 128 x 68
    float (*Ks)[QSTRIDE] = (float (*)[QSTRIDE])(sm + QROWS * QSTRIDE);    // 64 x 68
    float (*Vs)[QSTRIDE] = (float (*)[QSTRIDE])(sm + (QROWS + KTILE) * QSTRIDE);
    float (*Ps)[QSTRIDE] = (float (*)[QSTRIDE])(sm + (QROWS + 2 * KTILE) * QSTRIDE);

    const int tid = threadIdx.x;
    const int bh = blockIdx.y;        // 0..15
    const int b = bh >> 3, h = bh & 7;
    const int row0 = blockIdx.x * QROWS;
    const size_t headoff = (size_t)h * DEPTH;
    const size_t qbase  = ((size_t)(b * SEQ + row0)) * D_MODEL + headoff;
    const size_t kvbase = ((size_t)(b * SEQ)) * D_MODEL + headoff;

    // load Q tile [128 x 64] : 2048 float4, 16 per thread
    #pragma unroll
    for (int i = 0; i < 16; i++) {
        int lin = tid + i * 128;       // float4 index
        int r = lin >> 4;
        int c = (lin & 15) << 2;
        *(float4*)&Qs[r][c] = *(const float4*)&Q[qbase + (size_t)r * D_MODEL + c];
    }

    const int trow = tid >> 3;   // 0..15
    const int tcol = tid & 7;    // 0..7

    float mrow[8], lsum[8], O[8][8];
    #pragma unroll
    for (int r = 0; r < 8; r++) {
        mrow[r] = -3.0e38f;
        lsum[r] = 0.f;
        #pragma unroll
        for (int d = 0; d < 8; d++) O[r][d] = 0.f;
    }

    for (int t = 0; t < SEQ; t += KTILE) {
        __syncthreads();   // prev iter's K/V reads done
        #pragma unroll
        for (int i = 0; i < 8; i++) {
            int lin = tid + i * 128;   // 1024 float4 per tile
            int r = lin >> 4;
            int c = (lin & 15) << 2;
            size_t g = kvbase + (size_t)(t + r) * D_MODEL + c;
            *(float4*)&Ks[r][c] = *(const float4*)&K[g];
            *(float4*)&Vs[r][c] = *(const float4*)&V[g];
        }
        __syncthreads();   // tiles visible

        // ---- S = Q * K^T  (8x8 per thread) ----
        float s[8][8];
        #pragma unroll
        for (int r = 0; r < 8; r++)
            #pragma unroll
            for (int c = 0; c < 8; c++) s[r][c] = 0.f;

        #pragma unroll 4
        for (int kk = 0; kk < DEPTH; kk += 4) {
            float4 q4[8], k4[8];
            #pragma unroll
            for (int r = 0; r < 8; r++)
                q4[r] = *(const float4*)&Qs[trow + 16 * r][kk];
            #pragma unroll
            for (int c = 0; c < 8; c++)
                k4[c] = *(const float4*)&Ks[tcol + 8 * c][kk];
            #pragma unroll
            for (int r = 0; r < 8; r++)
                #pragma unroll
                for (int c = 0; c < 8; c++) {
                    s[r][c] += q4[r].x * k4[c].x;
                    s[r][c] += q4[r].y * k4[c].y;
                    s[r][c] += q4[r].z * k4[c].z;
                    s[r][c] += q4[r].w * k4[c].w;
                }
        }

        // ---- online softmax (log2 domain) ----
        #pragma unroll
        for (int r = 0; r < 8; r++) {
            float mx = s[r][0];
            #pragma unroll
            for (int c = 1; c < 8; c++) mx = fmaxf(mx, s[r][c]);
            mx = fmaxf(mx, __shfl_xor_sync(0xffffffffu, mx, 1));
            mx = fmaxf(mx, __shfl_xor_sync(0xffffffffu, mx, 2));
            mx = fmaxf(mx, __shfl_xor_sync(0xffffffffu, mx, 4));
            float mnew = fmaxf(mrow[r], mx);
            float corr = fast_ex2(mrow[r] - mnew);
            mrow[r] = mnew;
            float ls = 0.f;
            #pragma unroll
            for (int c = 0; c < 8; c++) {
                float p = fast_ex2(s[r][c] - mnew);
                s[r][c] = p;
                ls += p;
            }
            ls += __shfl_xor_sync(0xffffffffu, ls, 1);
            ls += __shfl_xor_sync(0xffffffffu, ls, 2);
            ls += __shfl_xor_sync(0xffffffffu, ls, 4);
            lsum[r] = lsum[r] * corr + ls;
            #pragma unroll
            for (int d = 0; d < 8; d++) O[r][d] *= corr;
            // store P (scalar, interleaved cols)
            #pragma unroll
            for (int c = 0; c < 8; c++)
                Ps[trow + 16 * r][tcol + 8 * c] = s[r][c];
        }
        __syncthreads();   // P visible

        // ---- O += P * V  (8 rows x 8 d per thread) ----
        #pragma unroll 4
        for (int c4 = 0; c4 < KTILE / 4; c4++) {
            float4 p4[8];
            #pragma unroll
            for (int r = 0; r < 8; r++)
                p4[r] = *(const float4*)&Ps[trow + 16 * r][c4 * 4];
            #pragma unroll
            for (int cc = 0; cc < 4; cc++) {
                float4 va = *(const float4*)&Vs[c4 * 4 + cc][tcol * 8];
                float4 vb = *(const float4*)&Vs[c4 * 4 + cc][tcol * 8 + 4];
                #pragma unroll
                for (int r = 0; r < 8; r++) {
                    float p = (cc == 0) ? p4[r].x : (cc == 1) ? p4[r].y
                            : (cc == 2) ? p4[r].z : p4[r].w;
                    O[r][0] += p * va.x; O[r][1] += p * va.y;
                    O[r][2] += p * va.z; O[r][3] += p * va.w;
                    O[r][4] += p * vb.x; O[r][5] += p * vb.y;
                    O[r][6] += p * vb.z; O[r][7] += p * vb.w;
                }
            }
        }
    }

    // ---- normalize + write [B,S,D] layout (head h occupies cols h*64..) ----
    #pragma unroll
    for (int r = 0; r < 8; r++) {
        float inv = 1.f / lsum[r];
        size_t addr = ((size_t)(b * SEQ + row0 + trow + 16 * r)) * D_MODEL
                    + headoff + tcol * 8;
        *(float4*)&Oout[addr] =
            make_float4(O[r][0] * inv, O[r][1] * inv, O[r][2] * inv, O[r][3] * inv);
        *(float4*)&Oout[addr + 4] =
            make_float4(O[r][4] * inv, O[r][5] * inv, O[r][6] * inv, O[r][7] * inv);
    }
}

// ---------------------------------------------------------------------------
extern "C" void kernel_launch(void* const* d_in, const int* in_sizes, int n_in,
                              void* d_out, int out_size)
{
    const float* x  = (const float*)d_in[0];
    const float* Wq = (const float*)d_in[1];
    const float* bq = (const float*)d_in[2];
    const float* Wk = (const float*)d_in[3];
    const float* bk = (const float*)d_in[4];
    const float* Wv = (const float*)d_in[5];
    const float* bv = (const float*)d_in[6];
    const float* Wo = (const float*)d_in[7];
    const float* bo = (const float*)d_in[8];
    float* out = (float*)d_out;

    float *q, *k, *v, *att;
    cudaGetSymbolAddress((void**)&q,   g_q);
    cudaGetSymbolAddress((void**)&k,   g_k);
    cudaGetSymbolAddress((void**)&v,   g_v);
    cudaGetSymbolAddress((void**)&att, g_att);

    dim3 pgrid(D_MODEL / 128, MROWS / 128);   // (4, 32)

    // Q projection: fold 1/sqrt(depth) AND log2(e) so attention works in exp2 domain
    gemm_bias<<<pgrid, 256>>>(x, Wq, bq, q, 0.125f * LOG2E);
    gemm_bias<<<pgrid, 256>>>(x, Wk, bk, k, 1.0f);
    gemm_bias<<<pgrid, 256>>>(x, Wv, bv, v, 1.0f);

    const int smem_bytes = (QROWS + 2 * KTILE + QROWS) * QSTRIDE * (int)sizeof(float); // 104448
    static int attr_set = 0;
    if (!attr_set) {
        cudaFuncSetAttribute(attn_kernel,
                             cudaFuncAttributeMaxDynamicSharedMemorySize, smem_bytes);
        attr_set = 1;
    }
    attn_kernel<<<dim3(SEQ / QROWS, BATCH * NHEADS), 128, smem_bytes>>>(q, k, v, att);

    gemm_bias<<<pgrid, 256>>>(att, Wo, bo, out, 1.0f);
}

// round 4
// speedup vs baseline: 3.1919x; 1.3358x over previous
#include <cuda_runtime.h>
#include <cuda_bf16.h>
#include <cstdint>
#include <cstddef>

#define D_MODEL 512
#define NHEADS  8
#define DEPTH   64
#define BATCH   2
#define SEQ     2048
#define MROWS   (BATCH*SEQ)   // 4096

#define LOG2E 1.4426950408889634f
#define QSTRIDE 68

#define QROWS 128
#define KTILE 64

// scratch (allocation-free rule: __device__ globals)
__device__ float g_q[MROWS * D_MODEL];
__device__ float g_k[MROWS * D_MODEL];
__device__ float g_v[MROWS * D_MODEL];
__device__ float g_att[MROWS * D_MODEL];
__device__ __nv_bfloat16 g_xh[MROWS * D_MODEL];   // activation hi (x, later att)
__device__ __nv_bfloat16 g_xl[MROWS * D_MODEL];   // activation lo
__device__ __nv_bfloat16 g_wh[D_MODEL * D_MODEL]; // weight hi (rotates per GEMM)
__device__ __nv_bfloat16 g_wl[D_MODEL * D_MODEL]; // weight lo

__device__ __forceinline__ float fast_ex2(float x) {
    float y;
    asm("ex2.approx.ftz.f32 %0, %1;" : "=f"(y) : "f"(x));
    return y;
}

__device__ __forceinline__ uint32_t smem_u32(const void* p) {
    uint32_t a;
    asm("{ .reg .u64 t; cvta.to.shared.u64 t, %1; cvt.u32.u64 %0, t; }"
        : "=r"(a) : "l"(p));
    return a;
}

// ===========================================================================
// fp32 -> bf16 hi/lo split conversion (grid-stride over float4)
// ===========================================================================
__global__ __launch_bounds__(256) void convert_hilo(
    const float* __restrict__ src, __nv_bfloat16* __restrict__ h,
    __nv_bfloat16* __restrict__ l, int n4)
{
    int i = blockIdx.x * blockDim.x + threadIdx.x;
    if (i >= n4) return;
    float4 f = ((const float4*)src)[i];
    __nv_bfloat16 h0 = __float2bfloat16(f.x);
    __nv_bfloat16 h1 = __float2bfloat16(f.y);
    __nv_bfloat16 h2 = __float2bfloat16(f.z);
    __nv_bfloat16 h3 = __float2bfloat16(f.w);
    __nv_bfloat16 l0 = __float2bfloat16(f.x - __bfloat162float(h0));
    __nv_bfloat16 l1 = __float2bfloat16(f.y - __bfloat162float(h1));
    __nv_bfloat16 l2 = __float2bfloat16(f.z - __bfloat162float(h2));
    __nv_bfloat16 l3 = __float2bfloat16(f.w - __bfloat162float(h3));
    ushort4 hv = make_ushort4(__bfloat16_as_ushort(h0), __bfloat16_as_ushort(h1),
                              __bfloat16_as_ushort(h2), __bfloat16_as_ushort(h3));
    ushort4 lv = make_ushort4(__bfloat16_as_ushort(l0), __bfloat16_as_ushort(l1),
                              __bfloat16_as_ushort(l2), __bfloat16_as_ushort(l3));
    ((ushort4*)h)[i] = hv;
    ((ushort4*)l)[i] = lv;
}

// ===========================================================================
// mma.sync bf16 GEMM: out[m,n] = (sum_k A[m,k]*W[n,k] + bias[n]) * alpha
// A, W given as hi/lo bf16 pairs (K contiguous, stride 512).
// D = Ah*Wh + Ah*Wl + Al*Wh.
// CTA tile 128x128, K-step 32, 256 threads (8 warps: 2 m x 4 n),
// warp tile 64x32 = 4x4 frags of m16n8k16. smem rows padded to 80B.
// ===========================================================================
#define SROW 80            // bytes per smem row (32 bf16 + 8 pad)
#define STILE (128*SROW)   // 10240 B per tile

#define LDSM_X4(r0,r1,r2,r3,addr) \
    asm volatile("ldmatrix.sync.aligned.m8n8.x4.shared.b16 {%0,%1,%2,%3}, [%4];" \
                 : "=r"(r0), "=r"(r1), "=r"(r2), "=r"(r3) : "r"(addr))

#define MMA16816(d0,d1,d2,d3,a0,a1,a2,a3,b0,b1) \
    asm volatile("mma.sync.aligned.m16n8k16.row.col.f32.bf16.bf16.f32 " \
                 "{%0,%1,%2,%3}, {%4,%5,%6,%7}, {%8,%9}, {%0,%1,%2,%3};" \
                 : "+f"(d0), "+f"(d1), "+f"(d2), "+f"(d3) \
                 : "r"(a0), "r"(a1), "r"(a2), "r"(a3), "r"(b0), "r"(b1))

__global__ __launch_bounds__(256) void gemm_mma(
    const __nv_bfloat16* __restrict__ Ah, const __nv_bfloat16* __restrict__ Al,
    const __nv_bfloat16* __restrict__ Wh, const __nv_bfloat16* __restrict__ Wl,
    const float* __restrict__ bias, float* __restrict__ out, float alpha)
{
    __shared__ __align__(16) char smem[4 * STILE];
    const uint32_t sbase = smem_u32(smem);
    const uint32_t SA_H = sbase, SA_L = sbase + STILE;
    const uint32_t SW_H = sbase + 2 * STILE, SW_L = sbase + 3 * STILE;

    const int tid = threadIdx.x;
    const int wid = tid >> 5, lane = tid & 31;
    const int wm = wid & 1, wn = wid >> 1;           // warp grid 2 x 4
    const int m0 = blockIdx.y * 128;
    const int n0 = blockIdx.x * 128;

    // loader mapping: row = tid>>1 (0..127), seg = tid&1 (k halves of 16)
    const int lrow = tid >> 1, lseg = tid & 1;
    const uint32_t soff = (uint32_t)lrow * SROW + (uint32_t)lseg * 32;
    const size_t ga_base = (size_t)(m0 + lrow) * D_MODEL + lseg * 16;
    const size_t gw_base = (size_t)(n0 + lrow) * D_MODEL + lseg * 16;

    // ldmatrix addresses (byte offsets into tiles)
    // A frag (per mi, ks): a0<-[m0-7,k0-7] a1<-[m8-15,k0-7] a2<-[m0-7,k8-15] a3<-[m8-15,k8-15]
    const uint32_t a_row = (uint32_t)(wm * 64 + (lane & 7) + ((lane >> 3) & 1) * 8);
    const uint32_t a_colb = (uint32_t)((lane >> 4) * 16);
    // B frag (per nb16, ks): r0<-[n0-7,k0-7] r1<-[n0-7,k8-15] r2<-[n8-15,k0-7] r3<-[n8-15,k8-15]
    const uint32_t b_row = (uint32_t)(wn * 32 + (lane & 7) + (lane >> 4) * 8);
    const uint32_t b_colb = (uint32_t)(((lane >> 3) & 1) * 16);

    float d[4][4][4];
    #pragma unroll
    for (int mi = 0; mi < 4; mi++)
        #pragma unroll
        for (int ni = 0; ni < 4; ni++)
            #pragma unroll
            for (int e = 0; e < 4; e++) d[mi][ni][e] = 0.f;

    for (int kc = 0; kc < D_MODEL / 32; kc++) {
        const int k0 = kc * 32;
        __syncthreads();
        // load 32 bf16 (two 16B chunks) per thread per array
        {
            uint4 v0 = *(const uint4*)(Ah + ga_base + k0);
            uint4 v1 = *(const uint4*)(Ah + ga_base + k0 + 8);
            *(uint4*)(smem + (SA_H - sbase) + soff) = v0;
            *(uint4*)(smem + (SA_H - sbase) + soff + 16) = v1;
            v0 = *(const uint4*)(Al + ga_base + k0);
            v1 = *(const uint4*)(Al + ga_base + k0 + 8);
            *(uint4*)(smem + (SA_L - sbase) + soff) = v0;
            *(uint4*)(smem + (SA_L - sbase) + soff + 16) = v1;
            v0 = *(const uint4*)(Wh + gw_base + k0);
            v1 = *(const uint4*)(Wh + gw_base + k0 + 8);
            *(uint4*)(smem + (SW_H - sbase) + soff) = v0;
            *(uint4*)(smem + (SW_H - sbase) + soff + 16) = v1;
            v0 = *(const uint4*)(Wl + gw_base + k0);
            v1 = *(const uint4*)(Wl + gw_base + k0 + 8);
            *(uint4*)(smem + (SW_L - sbase) + soff) = v0;
            *(uint4*)(smem + (SW_L - sbase) + soff + 16) = v1;
        }
        __syncthreads();

        #pragma unroll
        for (int ks = 0; ks < 2; ks++) {
            const uint32_t kb = (uint32_t)(ks * 32);
            uint32_t ah[4][4], al[4][4];
            #pragma unroll
            for (int mi = 0; mi < 4; mi++) {
                uint32_t addr = (a_row + mi * 16) * SROW + kb + a_colb;
                LDSM_X4(ah[mi][0], ah[mi][1], ah[mi][2], ah[mi][3], SA_H + addr);
                LDSM_X4(al[mi][0], al[mi][1], al[mi][2], al[mi][3], SA_L + addr);
            }
            uint32_t bh[4][2], bl[4][2];
            #pragma unroll
            for (int nb = 0; nb < 2; nb++) {
                uint32_t addr = (b_row + nb * 16) * SROW + kb + b_colb;
                uint32_t t0, t1, t2, t3;
                LDSM_X4(t0, t1, t2, t3, SW_H + addr);
                bh[2*nb][0] = t0; bh[2*nb][1] = t1;
                bh[2*nb+1][0] = t2; bh[2*nb+1][1] = t3;
                LDSM_X4(t0, t1, t2, t3, SW_L + addr);
                bl[2*nb][0] = t0; bl[2*nb][1] = t1;
                bl[2*nb+1][0] = t2; bl[2*nb+1][1] = t3;
            }
            #pragma unroll
            for (int mi = 0; mi < 4; mi++)
                #pragma unroll
                for (int ni = 0; ni < 4; ni++) {
                    MMA16816(d[mi][ni][0], d[mi][ni][1], d[mi][ni][2], d[mi][ni][3],
                             ah[mi][0], ah[mi][1], ah[mi][2], ah[mi][3],
                             bh[ni][0], bh[ni][1]);
                    MMA16816(d[mi][ni][0], d[mi][ni][1], d[mi][ni][2], d[mi][ni][3],
                             ah[mi][0], ah[mi][1], ah[mi][2], ah[mi][3],
                             bl[ni][0], bl[ni][1]);
                    MMA16816(d[mi][ni][0], d[mi][ni][1], d[mi][ni][2], d[mi][ni][3],
                             al[mi][0], al[mi][1], al[mi][2], al[mi][3],
                             bh[ni][0], bh[ni][1]);
                }
        }
    }

    // epilogue: accum layout: c0,c1 -> (row = m16 + lane/4, col = n8 + (lane%4)*2 +0,1)
    //           c2,c3 -> row + 8
    #pragma unroll
    for (int mi = 0; mi < 4; mi++) {
        int mrow = m0 + wm * 64 + mi * 16 + (lane >> 2);
        #pragma unroll
        for (int ni = 0; ni < 4; ni++) {
            int ncol = n0 + wn * 32 + ni * 8 + (lane & 3) * 2;
            float b0 = __ldg(bias + ncol), b1 = __ldg(bias + ncol + 1);
            float2 v0 = make_float2((d[mi][ni][0] + b0) * alpha,
                                    (d[mi][ni][1] + b1) * alpha);
            float2 v1 = make_float2((d[mi][ni][2] + b0) * alpha,
                                    (d[mi][ni][3] + b1) * alpha);
            *(float2*)&out[(size_t)mrow * D_MODEL + ncol] = v0;
            *(float2*)&out[(size_t)(mrow + 8) * D_MODEL + ncol] = v1;
        }
    }
}

// ---------------------------------------------------------------------------
// Flash attention, fp32, 8x8 per-thread tiles (unchanged from R2).
// ---------------------------------------------------------------------------
__global__ __launch_bounds__(128) void attn_kernel(
    const float* __restrict__ Q, const float* __restrict__ K,
    const float* __restrict__ V, float* __restrict__ Oout)
{
    extern __shared__ float sm[];
    float (*Qs)[QSTRIDE] = (float (*)[QSTRIDE])sm;
    float (*Ks)[QSTRIDE] = (float (*)[QSTRIDE])(sm + QROWS * QSTRIDE);
    float (*Vs)[QSTRIDE] = (float (*)[QSTRIDE])(sm + (QROWS + KTILE) * QSTRIDE);
    float (*Ps)[QSTRIDE] = (float (*)[QSTRIDE])(sm + (QROWS + 2 * KTILE) * QSTRIDE);

    const int tid = threadIdx.x;
    const int bh = blockIdx.y;
    const int b = bh >> 3, h = bh & 7;
    const int row0 = blockIdx.x * QROWS;
    const size_t headoff = (size_t)h * DEPTH;
    const size_t qbase  = ((size_t)(b * SEQ + row0)) * D_MODEL + headoff;
    const size_t kvbase = ((size_t)(b * SEQ)) * D_MODEL + headoff;

    #pragma unroll
    for (int i = 0; i < 16; i++) {
        int lin = tid + i * 128;
        int r = lin >> 4;
        int c = (lin & 15) << 2;
        *(float4*)&Qs[r][c] = *(const float4*)&Q[qbase + (size_t)r * D_MODEL + c];
    }

    const int trow = tid >> 3;
    const int tcol = tid & 7;

    float mrow[8], lsum[8], O[8][8];
    #pragma unroll
    for (int r = 0; r < 8; r++) {
        mrow[r] = -3.0e38f;
        lsum[r] = 0.f;
        #pragma unroll
        for (int d = 0; d < 8; d++) O[r][d] = 0.f;
    }

    for (int t = 0; t < SEQ; t += KTILE) {
        __syncthreads();
        #pragma unroll
        for (int i = 0; i < 8; i++) {
            int lin = tid + i * 128;
            int r = lin >> 4;
            int c = (lin & 15) << 2;
            size_t g = kvbase + (size_t)(t + r) * D_MODEL + c;
            *(float4*)&Ks[r][c] = *(const float4*)&K[g];
            *(float4*)&Vs[r][c] = *(const float4*)&V[g];
        }
        __syncthreads();

        float s[8][8];
        #pragma unroll
        for (int r = 0; r < 8; r++)
            #pragma unroll
            for (int c = 0; c < 8; c++) s[r][c] = 0.f;

        #pragma unroll 4
        for (int kk = 0; kk < DEPTH; kk += 4) {
            float4 q4[8], k4[8];
            #pragma unroll
            for (int r = 0; r < 8; r++)
                q4[r] = *(const float4*)&Qs[trow + 16 * r][kk];
            #pragma unroll
            for (int c = 0; c < 8; c++)
                k4[c] = *(const float4*)&Ks[tcol + 8 * c][kk];
            #pragma unroll
            for (int r = 0; r < 8; r++)
                #pragma unroll
                for (int c = 0; c < 8; c++) {
                    s[r][c] += q4[r].x * k4[c].x;
                    s[r][c] += q4[r].y * k4[c].y;
                    s[r][c] += q4[r].z * k4[c].z;
                    s[r][c] += q4[r].w * k4[c].w;
                }
        }

        #pragma unroll
        for (int r = 0; r < 8; r++) {
            float mx = s[r][0];
            #pragma unroll
            for (int c = 1; c < 8; c++) mx = fmaxf(mx, s[r][c]);
            mx = fmaxf(mx, __shfl_xor_sync(0xffffffffu, mx, 1));
            mx = fmaxf(mx, __shfl_xor_sync(0xffffffffu, mx, 2));
            mx = fmaxf(mx, __shfl_xor_sync(0xffffffffu, mx, 4));
            float mnew = fmaxf(mrow[r], mx);
            float corr = fast_ex2(mrow[r] - mnew);
            mrow[r] = mnew;
            float ls = 0.f;
            #pragma unroll
            for (int c = 0; c < 8; c++) {
                float p = fast_ex2(s[r][c] - mnew);
                s[r][c] = p;
                ls += p;
            }
            ls += __shfl_xor_sync(0xffffffffu, ls, 1);
            ls += __shfl_xor_sync(0xffffffffu, ls, 2);
            ls += __shfl_xor_sync(0xffffffffu, ls, 4);
            lsum[r] = lsum[r] * corr + ls;
            #pragma unroll
            for (int d = 0; d < 8; d++) O[r][d] *= corr;
            #pragma unroll
            for (int c = 0; c < 8; c++)
                Ps[trow + 16 * r][tcol + 8 * c] = s[r][c];
        }
        __syncthreads();

        #pragma unroll 4
        for (int c4 = 0; c4 < KTILE / 4; c4++) {
            float4 p4[8];
            #pragma unroll
            for (int r = 0; r < 8; r++)
                p4[r] = *(const float4*)&Ps[trow + 16 * r][c4 * 4];
            #pragma unroll
            for (int cc = 0; cc < 4; cc++) {
                float4 va = *(const float4*)&Vs[c4 * 4 + cc][tcol * 8];
                float4 vb = *(const float4*)&Vs[c4 * 4 + cc][tcol * 8 + 4];
                #pragma unroll
                for (int r = 0; r < 8; r++) {
                    float p = (cc == 0) ? p4[r].x : (cc == 1) ? p4[r].y
                            : (cc == 2) ? p4[r].z : p4[r].w;
                    O[r][0] += p * va.x; O[r][1] += p * va.y;
                    O[r][2] += p * va.z; O[r][3] += p * va.w;
                    O[r][4] += p * vb.x; O[r][5] += p * vb.y;
                    O[r][6] += p * vb.z; O[r][7] += p * vb.w;
                }
            }
        }
    }

    #pragma unroll
    for (int r = 0; r < 8; r++) {
        float inv = 1.f / lsum[r];
        size_t addr = ((size_t)(b * SEQ + row0 + trow + 16 * r)) * D_MODEL
                    + headoff + tcol * 8;
        *(float4*)&Oout[addr] =
            make_float4(O[r][0] * inv, O[r][1] * inv, O[r][2] * inv, O[r][3] * inv);
        *(float4*)&Oout[addr + 4] =
            make_float4(O[r][4] * inv, O[r][5] * inv, O[r][6] * inv, O[r][7] * inv);
    }
}

// ---------------------------------------------------------------------------
extern "C" void kernel_launch(void* const* d_in, const int* in_sizes, int n_in,
                              void* d_out, int out_size)
{
    const float* x  = (const float*)d_in[0];
    const float* Wq = (const float*)d_in[1];
    const float* bq = (const float*)d_in[2];
    const float* Wk = (const float*)d_in[3];
    const float* bk = (const float*)d_in[4];
    const float* Wv = (const float*)d_in[5];
    const float* bv = (const float*)d_in[6];
    const float* Wo = (const float*)d_in[7];
    const float* bo = (const float*)d_in[8];
    float* out = (float*)d_out;

    float *q, *k, *v, *att;
    __nv_bfloat16 *xh, *xl, *wh, *wl;
    cudaGetSymbolAddress((void**)&q,   g_q);
    cudaGetSymbolAddress((void**)&k,   g_k);
    cudaGetSymbolAddress((void**)&v,   g_v);
    cudaGetSymbolAddress((void**)&att, g_att);
    cudaGetSymbolAddress((void**)&xh,  g_xh);
    cudaGetSymbolAddress((void**)&xl,  g_xl);
    cudaGetSymbolAddress((void**)&wh,  g_wh);
    cudaGetSymbolAddress((void**)&wl,  g_wl);

    const int xn4 = MROWS * D_MODEL / 4;      // 524288
    const int wn4 = D_MODEL * D_MODEL / 4;    // 65536
    dim3 pgrid(D_MODEL / 128, MROWS / 128);   // (4, 32)

    convert_hilo<<<xn4 / 256, 256>>>(x, xh, xl, xn4);

    convert_hilo<<<wn4 / 256, 256>>>(Wq, wh, wl, wn4);
    gemm_mma<<<pgrid, 256>>>(xh, xl, wh, wl, bq, q, 0.125f * LOG2E);

    convert_hilo<<<wn4 / 256, 256>>>(Wk, wh, wl, wn4);
    gemm_mma<<<pgrid, 256>>>(xh, xl, wh, wl, bk, k, 1.0f);

    convert_hilo<<<wn4 / 256, 256>>>(Wv, wh, wl, wn4);
    gemm_mma<<<pgrid, 256>>>(xh, xl, wh, wl, bv, v, 1.0f);

    const int attn_smem = (QROWS + 2 * KTILE + QROWS) * QSTRIDE * (int)sizeof(float);
    cudaFuncSetAttribute(attn_kernel,
                         cudaFuncAttributeMaxDynamicSharedMemorySize, attn_smem);
    attn_kernel<<<dim3(SEQ / QROWS, BATCH * NHEADS), 128, attn_smem>>>(q, k, v, att);

    // reuse xh/xl for the attention output activation
    convert_hilo<<<xn4 / 256, 256>>>(att, xh, xl, xn4);
    convert_hilo<<<wn4 / 256, 256>>>(Wo, wh, wl, wn4);
    gemm_mma<<<pgrid, 256>>>(xh, xl, wh, wl, bo, out, 1.0f);
}

// round 5
// speedup vs baseline: 6.1343x; 1.9218x over previous
#include <cuda_runtime.h>
#include <cuda_bf16.h>
#include <cstdint>
#include <cstddef>

#define D_MODEL 512
#define NHEADS  8
#define DEPTH   64
#define BATCH   2
#define SEQ     2048
#define MROWS   (BATCH*SEQ)   // 4096

#define LOG2E 1.4426950408889634f

// bf16 hi/lo scratch (allocation-free rule: __device__ globals)
__device__ __nv_bfloat16 g_xh[MROWS * D_MODEL];   // x hi, later attn-out hi
__device__ __nv_bfloat16 g_xl[MROWS * D_MODEL];
__device__ __nv_bfloat16 g_qh[MROWS * D_MODEL];
__device__ __nv_bfloat16 g_ql[MROWS * D_MODEL];
__device__ __nv_bfloat16 g_kh[MROWS * D_MODEL];
__device__ __nv_bfloat16 g_kl[MROWS * D_MODEL];
__device__ __nv_bfloat16 g_vh[MROWS * D_MODEL];
__device__ __nv_bfloat16 g_vl[MROWS * D_MODEL];
__device__ __nv_bfloat16 g_wh[D_MODEL * D_MODEL];
__device__ __nv_bfloat16 g_wl[D_MODEL * D_MODEL];

__device__ __forceinline__ float fast_ex2(float x) {
    float y;
    asm("ex2.approx.ftz.f32 %0, %1;" : "=f"(y) : "f"(x));
    return y;
}
__device__ __forceinline__ uint32_t smem_u32(const void* p) {
    uint32_t a;
    asm("{ .reg .u64 t; cvta.to.shared.u64 t, %1; cvt.u32.u64 %0, t; }"
        : "=r"(a) : "l"(p));
    return a;
}
// pack two fp32 -> bf16x2 (hi goes to upper 16 bits)
__device__ __forceinline__ uint32_t packbf(float hi, float lo) {
    uint32_t r;
    asm("cvt.rn.bf16x2.f32 %0, %1, %2;" : "=r"(r) : "f"(hi), "f"(lo));
    return r;
}
__device__ __forceinline__ float lo_f(uint32_t p) { return __uint_as_float(p << 16); }
__device__ __forceinline__ float hi_f(uint32_t p) { return __uint_as_float(p & 0xffff0000u); }

#define LDSM_X4(r0,r1,r2,r3,addr) \
    asm volatile("ldmatrix.sync.aligned.m8n8.x4.shared.b16 {%0,%1,%2,%3}, [%4];" \
                 : "=r"(r0), "=r"(r1), "=r"(r2), "=r"(r3) : "r"(addr))
#define LDSM_X4T(r0,r1,r2,r3,addr) \
    asm volatile("ldmatrix.sync.aligned.m8n8.x4.trans.shared.b16 {%0,%1,%2,%3}, [%4];" \
                 : "=r"(r0), "=r"(r1), "=r"(r2), "=r"(r3) : "r"(addr))
#define MMA16816(d0,d1,d2,d3,a0,a1,a2,a3,b0,b1) \
    asm volatile("mma.sync.aligned.m16n8k16.row.col.f32.bf16.bf16.f32 " \
                 "{%0,%1,%2,%3}, {%4,%5,%6,%7}, {%8,%9}, {%0,%1,%2,%3};" \
                 : "+f"(d0), "+f"(d1), "+f"(d2), "+f"(d3) \
                 : "r"(a0), "r"(a1), "r"(a2), "r"(a3), "r"(b0), "r"(b1))

// ===========================================================================
// fp32 -> bf16 hi/lo split
// ===========================================================================
__global__ __launch_bounds__(256) void convert_hilo(
    const float* __restrict__ src, __nv_bfloat16* __restrict__ h,
    __nv_bfloat16* __restrict__ l, int n4)
{
    int i = blockIdx.x * blockDim.x + threadIdx.x;
    if (i >= n4) return;
    float4 f = ((const float4*)src)[i];
    uint32_t h01 = packbf(f.y, f.x);
    uint32_t h23 = packbf(f.w, f.z);
    uint32_t l01 = packbf(f.y - hi_f(h01), f.x - lo_f(h01));
    uint32_t l23 = packbf(f.w - hi_f(h23), f.z - lo_f(h23));
    ((uint2*)h)[i] = make_uint2(h01, h23);
    ((uint2*)l)[i] = make_uint2(l01, l23);
}

// ===========================================================================
// mma.sync bf16 GEMM: out[m,n] = (sum_k A[m,k]*W[n,k] + bias[n]) * alpha
// D = Ah*Wh + Ah*Wl + Al*Wh. CTA 128x128, K-step 32, 256 threads (2x4 warps),
// warp tile 64x32. Epilogue: fp32 (outf) OR bf16 hi/lo (outh/outl).
// ===========================================================================
#define SROW 80
#define STILE (128*SROW)

__global__ __launch_bounds__(256) void gemm_mma(
    const __nv_bfloat16* __restrict__ Ah, const __nv_bfloat16* __restrict__ Al,
    const __nv_bfloat16* __restrict__ Wh, const __nv_bfloat16* __restrict__ Wl,
    const float* __restrict__ bias, float* __restrict__ outf,
    __nv_bfloat16* __restrict__ outh, __nv_bfloat16* __restrict__ outl,
    float alpha)
{
    __shared__ __align__(16) char smem[4 * STILE];
    const uint32_t sbase = smem_u32(smem);
    const uint32_t SA_H = sbase, SA_L = sbase + STILE;
    const uint32_t SW_H = sbase + 2 * STILE, SW_L = sbase + 3 * STILE;

    const int tid = threadIdx.x;
    const int wid = tid >> 5, lane = tid & 31;
    const int wm = wid & 1, wn = wid >> 1;
    const int m0 = blockIdx.y * 128;
    const int n0 = blockIdx.x * 128;

    const int lrow = tid >> 1, lseg = tid & 1;
    const uint32_t soff = (uint32_t)lrow * SROW + (uint32_t)lseg * 32;
    const size_t ga_base = (size_t)(m0 + lrow) * D_MODEL + lseg * 16;
    const size_t gw_base = (size_t)(n0 + lrow) * D_MODEL + lseg * 16;

    const uint32_t a_row = (uint32_t)(wm * 64 + (lane & 7) + ((lane >> 3) & 1) * 8);
    const uint32_t a_colb = (uint32_t)((lane >> 4) * 16);
    const uint32_t b_row = (uint32_t)(wn * 32 + (lane & 7) + (lane >> 4) * 8);
    const uint32_t b_colb = (uint32_t)(((lane >> 3) & 1) * 16);

    float d[4][4][4];
    #pragma unroll
    for (int mi = 0; mi < 4; mi++)
        #pragma unroll
        for (int ni = 0; ni < 4; ni++)
            #pragma unroll
            for (int e = 0; e < 4; e++) d[mi][ni][e] = 0.f;

    for (int kc = 0; kc < D_MODEL / 32; kc++) {
        const int k0 = kc * 32;
        __syncthreads();
        {
            uint4 v0 = *(const uint4*)(Ah + ga_base + k0);
            uint4 v1 = *(const uint4*)(Ah + ga_base + k0 + 8);
            *(uint4*)(smem + (SA_H - sbase) + soff) = v0;
            *(uint4*)(smem + (SA_H - sbase) + soff + 16) = v1;
            v0 = *(const uint4*)(Al + ga_base + k0);
            v1 = *(const uint4*)(Al + ga_base + k0 + 8);
            *(uint4*)(smem + (SA_L - sbase) + soff) = v0;
            *(uint4*)(smem + (SA_L - sbase) + soff + 16) = v1;
            v0 = *(const uint4*)(Wh + gw_base + k0);
            v1 = *(const uint4*)(Wh + gw_base + k0 + 8);
            *(uint4*)(smem + (SW_H - sbase) + soff) = v0;
            *(uint4*)(smem + (SW_H - sbase) + soff + 16) = v1;
            v0 = *(const uint4*)(Wl + gw_base + k0);
            v1 = *(const uint4*)(Wl + gw_base + k0 + 8);
            *(uint4*)(smem + (SW_L - sbase) + soff) = v0;
            *(uint4*)(smem + (SW_L - sbase) + soff + 16) = v1;
        }
        __syncthreads();

        #pragma unroll
        for (int ks = 0; ks < 2; ks++) {
            const uint32_t kb = (uint32_t)(ks * 32);
            uint32_t ah[4][4], al[4][4];
            #pragma unroll
            for (int mi = 0; mi < 4; mi++) {
                uint32_t addr = (a_row + mi * 16) * SROW + kb + a_colb;
                LDSM_X4(ah[mi][0], ah[mi][1], ah[mi][2], ah[mi][3], SA_H + addr);
                LDSM_X4(al[mi][0], al[mi][1], al[mi][2], al[mi][3], SA_L + addr);
            }
            uint32_t bh[4][2], bl[4][2];
            #pragma unroll
            for (int nb = 0; nb < 2; nb++) {
                uint32_t addr = (b_row + nb * 16) * SROW + kb + b_colb;
                uint32_t t0, t1, t2, t3;
                LDSM_X4(t0, t1, t2, t3, SW_H + addr);
                bh[2*nb][0] = t0; bh[2*nb][1] = t1;
                bh[2*nb+1][0] = t2; bh[2*nb+1][1] = t3;
                LDSM_X4(t0, t1, t2, t3, SW_L + addr);
                bl[2*nb][0] = t0; bl[2*nb][1] = t1;
                bl[2*nb+1][0] = t2; bl[2*nb+1][1] = t3;
            }
            #pragma unroll
            for (int mi = 0; mi < 4; mi++)
                #pragma unroll
                for (int ni = 0; ni < 4; ni++) {
                    MMA16816(d[mi][ni][0], d[mi][ni][1], d[mi][ni][2], d[mi][ni][3],
                             ah[mi][0], ah[mi][1], ah[mi][2], ah[mi][3],
                             bh[ni][0], bh[ni][1]);
                    MMA16816(d[mi][ni][0], d[mi][ni][1], d[mi][ni][2], d[mi][ni][3],
                             ah[mi][0], ah[mi][1], ah[mi][2], ah[mi][3],
                             bl[ni][0], bl[ni][1]);
                    MMA16816(d[mi][ni][0], d[mi][ni][1], d[mi][ni][2], d[mi][ni][3],
                             al[mi][0], al[mi][1], al[mi][2], al[mi][3],
                             bh[ni][0], bh[ni][1]);
                }
        }
    }

    #pragma unroll
    for (int mi = 0; mi < 4; mi++) {
        int mrow = m0 + wm * 64 + mi * 16 + (lane >> 2);
        #pragma unroll
        for (int ni = 0; ni < 4; ni++) {
            int ncol = n0 + wn * 32 + ni * 8 + (lane & 3) * 2;
            float b0 = __ldg(bias + ncol), b1 = __ldg(bias + ncol + 1);
            float v0 = (d[mi][ni][0] + b0) * alpha;
            float v1 = (d[mi][ni][1] + b1) * alpha;
            float v2 = (d[mi][ni][2] + b0) * alpha;
            float v3 = (d[mi][ni][3] + b1) * alpha;
            size_t e0 = (size_t)mrow * D_MODEL + ncol;
            size_t e1 = (size_t)(mrow + 8) * D_MODEL + ncol;
            if (outh) {
                uint32_t h01 = packbf(v1, v0);
                uint32_t h23 = packbf(v3, v2);
                uint32_t l01 = packbf(v1 - hi_f(h01), v0 - lo_f(h01));
                uint32_t l23 = packbf(v3 - hi_f(h23), v2 - lo_f(h23));
                ((uint32_t*)outh)[e0 >> 1] = h01;
                ((uint32_t*)outl)[e0 >> 1] = l01;
                ((uint32_t*)outh)[e1 >> 1] = h23;
                ((uint32_t*)outl)[e1 >> 1] = l23;
            } else {
                *(float2*)&outf[e0] = make_float2(v0, v1);
                *(float2*)&outf[e1] = make_float2(v2, v3);
            }
        }
    }
}

// ===========================================================================
// Flash attention on mma.sync. Grid (SEQ/128, B*H), 128 threads (4 warps).
// Warp owns 32 q-rows (2 m16 frags). KV tile 64. S: Q[.,64] x K[64,64]^T via
// row.col (both K-major). PV: A = P frags (register reuse of S accum layout),
// B = V via ldmatrix.trans. 3-term hi/lo split on both GEMMs.
// smem: union{ Qstage hi/lo [2][128][72] | tiles kh/kl/vh/vl [4][64][72] }.
// ===========================================================================
#define ASTRIDE 72         // bf16 per smem row (144 B)
#define ATILE_B (64*144)   // 9216 B per tile

__global__ __launch_bounds__(128) void attn_mma(
    const __nv_bfloat16* __restrict__ Qh, const __nv_bfloat16* __restrict__ Ql,
    const __nv_bfloat16* __restrict__ Kh, const __nv_bfloat16* __restrict__ Kl,
    const __nv_bfloat16* __restrict__ Vh, const __nv_bfloat16* __restrict__ Vl,
    __nv_bfloat16* __restrict__ Oh, __nv_bfloat16* __restrict__ Ol)
{
    __shared__ __align__(16) __nv_bfloat16 sbuf[4 * 64 * ASTRIDE]; // 36864 B
    const uint32_t sb = smem_u32(sbuf);

    const int tid = threadIdx.x;
    const int wid = tid >> 5, lane = tid & 31;
    const int bh = blockIdx.y;
    const int b = bh >> 3, h = bh & 7;
    const int row0 = blockIdx.x * 128;
    const size_t qbase  = ((size_t)(b * SEQ + row0)) * D_MODEL + h * 64;
    const size_t kvbase = ((size_t)(b * SEQ)) * D_MODEL + h * 64;

    // ---- stage Q hi/lo (as [2][128][72]) and load A-frags ----
    #pragma unroll
    for (int i = 0; i < 8; i++) {
        int lin = tid + i * 128;          // 1024 chunks of 8 bf16
        int r = lin >> 3, c = (lin & 7) * 8;
        size_t g = qbase + (size_t)r * D_MODEL + c;
        *(uint4*)&sbuf[r * ASTRIDE + c] = *(const uint4*)&Qh[g];
        *(uint4*)&sbuf[128 * ASTRIDE + r * ASTRIDE + c] = *(const uint4*)&Ql[g];
    }
    __syncthreads();

    uint32_t qfh[2][4][4], qfl[2][4][4];
    {
        uint32_t arow = (uint32_t)(wid * 32 + (lane & 7) + ((lane >> 3) & 1) * 8);
        uint32_t acol = (uint32_t)((lane >> 4) * 16);
        #pragma unroll
        for (int mi = 0; mi < 2; mi++)
            #pragma unroll
            for (int kc = 0; kc < 4; kc++) {
                uint32_t ad = sb + (arow + mi * 16) * 144 + kc * 32 + acol;
                LDSM_X4(qfh[mi][kc][0], qfh[mi][kc][1], qfh[mi][kc][2], qfh[mi][kc][3], ad);
                LDSM_X4(qfl[mi][kc][0], qfl[mi][kc][1], qfl[mi][kc][2], qfl[mi][kc][3],
                        ad + 128 * 144);
            }
    }

    float m_[2][2], l_[2][2], o[2][8][4];
    #pragma unroll
    for (int mi = 0; mi < 2; mi++) {
        m_[mi][0] = m_[mi][1] = -3.0e38f;
        l_[mi][0] = l_[mi][1] = 0.f;
        #pragma unroll
        for (int nd = 0; nd < 8; nd++)
            #pragma unroll
            for (int e = 0; e < 4; e++) o[mi][nd][e] = 0.f;
    }

    const uint32_t S_KH = sb, S_KL = sb + ATILE_B;
    const uint32_t S_VH = sb + 2 * ATILE_B, S_VL = sb + 3 * ATILE_B;

    for (int t = 0; t < SEQ; t += 64) {
        __syncthreads();   // prior smem reads (Q frags on iter 0) complete
        #pragma unroll
        for (int i = 0; i < 4; i++) {
            int lin = tid + i * 128;     // 512 chunks per array
            int r = lin >> 3, c = (lin & 7) * 8;
            size_t g = kvbase + (size_t)(t + r) * D_MODEL + c;
            uint32_t so = (uint32_t)(r * ASTRIDE + c);
            *(uint4*)&sbuf[0 * 64 * ASTRIDE + so] = *(const uint4*)&Kh[g];
            *(uint4*)&sbuf[1 * 64 * ASTRIDE + so] = *(const uint4*)&Kl[g];
            *(uint4*)&sbuf[2 * 64 * ASTRIDE + so] = *(const uint4*)&Vh[g];
            *(uint4*)&sbuf[3 * 64 * ASTRIDE + so] = *(const uint4*)&Vl[g];
        }
        __syncthreads();

        // ---- S = Q K^T (3-term) ----
        float s[2][8][4];
        #pragma unroll
        for (int mi = 0; mi < 2; mi++)
            #pragma unroll
            for (int ni = 0; ni < 8; ni++)
                #pragma unroll
                for (int e = 0; e < 4; e++) s[mi][ni][e] = 0.f;

        #pragma unroll
        for (int kc = 0; kc < 4; kc++) {
            uint32_t kbh[8][2], kbl[8][2];
            uint32_t brow = (uint32_t)((lane & 7) + (lane >> 4) * 8);
            uint32_t bcol = (uint32_t)(kc * 32 + ((lane >> 3) & 1) * 16);
            #pragma unroll
            for (int nb = 0; nb < 4; nb++) {
                uint32_t ad = (brow + nb * 16) * 144 + bcol;
                uint32_t t0, t1, t2, t3;
                LDSM_X4(t0, t1, t2, t3, S_KH + ad);
                kbh[2*nb][0] = t0; kbh[2*nb][1] = t1;
                kbh[2*nb+1][0] = t2; kbh[2*nb+1][1] = t3;
                LDSM_X4(t0, t1, t2, t3, S_KL + ad);
                kbl[2*nb][0] = t0; kbl[2*nb][1] = t1;
                kbl[2*nb+1][0] = t2; kbl[2*nb+1][1] = t3;
            }
            #pragma unroll
            for (int mi = 0; mi < 2; mi++)
                #pragma unroll
                for (int ni = 0; ni < 8; ni++) {
                    MMA16816(s[mi][ni][0], s[mi][ni][1], s[mi][ni][2], s[mi][ni][3],
                             qfh[mi][kc][0], qfh[mi][kc][1], qfh[mi][kc][2], qfh[mi][kc][3],
                             kbh[ni][0], kbh[ni][1]);
                    MMA16816(s[mi][ni][0], s[mi][ni][1], s[mi][ni][2], s[mi][ni][3],
                             qfh[mi][kc][0], qfh[mi][kc][1], qfh[mi][kc][2], qfh[mi][kc][3],
                             kbl[ni][0], kbl[ni][1]);
                    MMA16816(s[mi][ni][0], s[mi][ni][1], s[mi][ni][2], s[mi][ni][3],
                             qfl[mi][kc][0], qfl[mi][kc][1], qfl[mi][kc][2], qfl[mi][kc][3],
                             kbh[ni][0], kbh[ni][1]);
                }
        }

        // ---- online softmax (log2 domain; Q pre-scaled by 0.125*log2e) ----
        uint32_t ph0[2][8], ph1[2][8], pl0[2][8], pl1[2][8];
        #pragma unroll
        for (int mi = 0; mi < 2; mi++) {
            float mx0 = -3.0e38f, mx1 = -3.0e38f;
            #pragma unroll
            for (int ni = 0; ni < 8; ni++) {
                mx0 = fmaxf(mx0, fmaxf(s[mi][ni][0], s[mi][ni][1]));
                mx1 = fmaxf(mx1, fmaxf(s[mi][ni][2], s[mi][ni][3]));
            }
            mx0 = fmaxf(mx0, __shfl_xor_sync(0xffffffffu, mx0, 1));
            mx0 = fmaxf(mx0, __shfl_xor_sync(0xffffffffu, mx0, 2));
            mx1 = fmaxf(mx1, __shfl_xor_sync(0xffffffffu, mx1, 1));
            mx1 = fmaxf(mx1, __shfl_xor_sync(0xffffffffu, mx1, 2));
            float mn0 = fmaxf(m_[mi][0], mx0);
            float mn1 = fmaxf(m_[mi][1], mx1);
            float c0 = fast_ex2(m_[mi][0] - mn0);
            float c1 = fast_ex2(m_[mi][1] - mn1);
            m_[mi][0] = mn0; m_[mi][1] = mn1;
            float s0 = 0.f, s1 = 0.f;
            #pragma unroll
            for (int ni = 0; ni < 8; ni++) {
                float p0 = fast_ex2(s[mi][ni][0] - mn0);
                float p1 = fast_ex2(s[mi][ni][1] - mn0);
                float p2 = fast_ex2(s[mi][ni][2] - mn1);
                float p3 = fast_ex2(s[mi][ni][3] - mn1);
                s0 += p0 + p1; s1 += p2 + p3;
                uint32_t h01 = packbf(p1, p0);
                uint32_t h23 = packbf(p3, p2);
                ph0[mi][ni] = h01; ph1[mi][ni] = h23;
                pl0[mi][ni] = packbf(p1 - hi_f(h01), p0 - lo_f(h01));
                pl1[mi][ni] = packbf(p3 - hi_f(h23), p2 - lo_f(h23));
            }
            s0 += __shfl_xor_sync(0xffffffffu, s0, 1);
            s0 += __shfl_xor_sync(0xffffffffu, s0, 2);
            s1 += __shfl_xor_sync(0xffffffffu, s1, 1);
            s1 += __shfl_xor_sync(0xffffffffu, s1, 2);
            l_[mi][0] = l_[mi][0] * c0 + s0;
            l_[mi][1] = l_[mi][1] * c1 + s1;
            #pragma unroll
            for (int nd = 0; nd < 8; nd++) {
                o[mi][nd][0] *= c0; o[mi][nd][1] *= c0;
                o[mi][nd][2] *= c1; o[mi][nd][3] *= c1;
            }
        }

        // ---- O += P V (3-term; V frags via ldmatrix.trans) ----
        #pragma unroll
        for (int kt = 0; kt < 4; kt++) {
            uint32_t vbh[8][2], vbl[8][2];
            uint32_t vrow = (uint32_t)(kt * 16 + (lane & 7) + ((lane >> 3) & 1) * 8);
            #pragma unroll
            for (int np = 0; np < 4; np++) {
                uint32_t ad = vrow * 144 + (uint32_t)(np * 32 + (lane >> 4) * 16);
                uint32_t t0, t1, t2, t3;
                LDSM_X4T(t0, t1, t2, t3, S_VH + ad);
                vbh[2*np][0] = t0; vbh[2*np][1] = t1;
                vbh[2*np+1][0] = t2; vbh[2*np+1][1] = t3;
                LDSM_X4T(t0, t1, t2, t3, S_VL + ad);
                vbl[2*np][0] = t0; vbl[2*np][1] = t1;
                vbl[2*np+1][0] = t2; vbl[2*np+1][1] = t3;
            }
            #pragma unroll
            for (int mi = 0; mi < 2; mi++) {
                uint32_t a0 = ph0[mi][2*kt],   a1 = ph1[mi][2*kt];
                uint32_t a2 = ph0[mi][2*kt+1], a3 = ph1[mi][2*kt+1];
                uint32_t r0 = pl0[mi][2*kt],   r1 = pl1[mi][2*kt];
                uint32_t r2 = pl0[mi][2*kt+1], r3 = pl1[mi][2*kt+1];
                #pragma unroll
                for (int nd = 0; nd < 8; nd++) {
                    MMA16816(o[mi][nd][0], o[mi][nd][1], o[mi][nd][2], o[mi][nd][3],
                             a0, a1, a2, a3, vbh[nd][0], vbh[nd][1]);
                    MMA16816(o[mi][nd][0], o[mi][nd][1], o[mi][nd][2], o[mi][nd][3],
                             a0, a1, a2, a3, vbl[nd][0], vbl[nd][1]);
                    MMA16816(o[mi][nd][0], o[mi][nd][1], o[mi][nd][2], o[mi][nd][3],
                             r0, r1, r2, r3, vbh[nd][0], vbh[nd][1]);
                }
            }
        }
    }

    // ---- normalize, split hi/lo, store ----
    #pragma unroll
    for (int mi = 0; mi < 2; mi++)
        #pragma unroll
        for (int hh = 0; hh < 2; hh++) {
            float inv = 1.f / l_[mi][hh];
            int r = row0 + wid * 32 + mi * 16 + (lane >> 2) + hh * 8;
            size_t base = ((size_t)(b * SEQ + r)) * D_MODEL + h * 64 + (lane & 3) * 2;
            #pragma unroll
            for (int nd = 0; nd < 8; nd++) {
                float v0 = o[mi][nd][2*hh]     * inv;
                float v1 = o[mi][nd][2*hh + 1] * inv;
                uint32_t hp = packbf(v1, v0);
                uint32_t lp = packbf(v1 - hi_f(hp), v0 - lo_f(hp));
                size_t e = base + nd * 8;
                ((uint32_t*)Oh)[e >> 1] = hp;
                ((uint32_t*)Ol)[e >> 1] = lp;
            }
        }
}

// ---------------------------------------------------------------------------
extern "C" void kernel_launch(void* const* d_in, const int* in_sizes, int n_in,
                              void* d_out, int out_size)
{
    const float* x  = (const float*)d_in[0];
    const float* Wq = (const float*)d_in[1];
    const float* bq = (const float*)d_in[2];
    const float* Wk = (const float*)d_in[3];
    const float* bk = (const float*)d_in[4];
    const float* Wv = (const float*)d_in[5];
    const float* bv = (const float*)d_in[6];
    const float* Wo = (const float*)d_in[7];
    const float* bo = (const float*)d_in[8];
    float* out = (float*)d_out;

    __nv_bfloat16 *xh, *xl, *qh, *ql, *kh, *kl, *vh, *vl, *wh, *wl;
    cudaGetSymbolAddress((void**)&xh, g_xh);
    cudaGetSymbolAddress((void**)&xl, g_xl);
    cudaGetSymbolAddress((void**)&qh, g_qh);
    cudaGetSymbolAddress((void**)&ql, g_ql);
    cudaGetSymbolAddress((void**)&kh, g_kh);
    cudaGetSymbolAddress((void**)&kl, g_kl);
    cudaGetSymbolAddress((void**)&vh, g_vh);
    cudaGetSymbolAddress((void**)&vl, g_vl);
    cudaGetSymbolAddress((void**)&wh, g_wh);
    cudaGetSymbolAddress((void**)&wl, g_wl);

    const int xn4 = MROWS * D_MODEL / 4;
    const int wn4 = D_MODEL * D_MODEL / 4;
    dim3 pgrid(D_MODEL / 128, MROWS / 128);   // (4, 32)

    convert_hilo<<<xn4 / 256, 256>>>(x, xh, xl, xn4);

    convert_hilo<<<wn4 / 256, 256>>>(Wq, wh, wl, wn4);
    gemm_mma<<<pgrid, 256>>>(xh, xl, wh, wl, bq, nullptr, qh, ql, 0.125f * LOG2E);

    convert_hilo<<<wn4 / 256, 256>>>(Wk, wh, wl, wn4);
    gemm_mma<<<pgrid, 256>>>(xh, xl, wh, wl, bk, nullptr, kh, kl, 1.0f);

    convert_hilo<<<wn4 / 256, 256>>>(Wv, wh, wl, wn4);
    gemm_mma<<<pgrid, 256>>>(xh, xl, wh, wl, bv, nullptr, vh, vl, 1.0f);

    // attention reads q/k/v hi-lo, writes its output into xh/xl (x is dead)
    attn_mma<<<dim3(SEQ / 128, BATCH * NHEADS), 128>>>(qh, ql, kh, kl, vh, vl, xh, xl);

    convert_hilo<<<wn4 / 256, 256>>>(Wo, wh, wl, wn4);
    gemm_mma<<<pgrid, 256>>>(xh, xl, wh, wl, bo, out, nullptr, nullptr, 1.0f);
}

// round 6
// speedup vs baseline: 6.5142x; 1.0619x over previous
#include <cuda_runtime.h>
#include <cuda_bf16.h>
#include <cstdint>
#include <cstddef>

#define D_MODEL 512
#define NHEADS  8
#define DEPTH   64
#define BATCH   2
#define SEQ     2048
#define MROWS   (BATCH*SEQ)   // 4096

#define LOG2E 1.4426950408889634f

// bf16 hi/lo scratch (allocation-free rule: __device__ globals)
__device__ __nv_bfloat16 g_xh[MROWS * D_MODEL];   // x hi, later attn-out hi
__device__ __nv_bfloat16 g_xl[MROWS * D_MODEL];
__device__ __nv_bfloat16 g_qh[MROWS * D_MODEL];
__device__ __nv_bfloat16 g_ql[MROWS * D_MODEL];
__device__ __nv_bfloat16 g_kh[MROWS * D_MODEL];
__device__ __nv_bfloat16 g_kl[MROWS * D_MODEL];
__device__ __nv_bfloat16 g_vh[MROWS * D_MODEL];
__device__ __nv_bfloat16 g_vl[MROWS * D_MODEL];
__device__ __nv_bfloat16 g_wh[4 * D_MODEL * D_MODEL];  // Wq,Wk,Wv,Wo hi
__device__ __nv_bfloat16 g_wl[4 * D_MODEL * D_MODEL];  // lo

__device__ __forceinline__ float fast_ex2(float x) {
    float y;
    asm("ex2.approx.ftz.f32 %0, %1;" : "=f"(y) : "f"(x));
    return y;
}
__device__ __forceinline__ uint32_t smem_u32(const void* p) {
    uint32_t a;
    asm("{ .reg .u64 t; cvta.to.shared.u64 t, %1; cvt.u32.u64 %0, t; }"
        : "=r"(a) : "l"(p));
    return a;
}
__device__ __forceinline__ uint32_t packbf(float hi, float lo) {
    uint32_t r;
    asm("cvt.rn.bf16x2.f32 %0, %1, %2;" : "=r"(r) : "f"(hi), "f"(lo));
    return r;
}
__device__ __forceinline__ float lo_f(uint32_t p) { return __uint_as_float(p << 16); }
__device__ __forceinline__ float hi_f(uint32_t p) { return __uint_as_float(p & 0xffff0000u); }

__device__ __forceinline__ void cp16(uint32_t s, const void* g) {
    asm volatile("cp.async.cg.shared.global [%0], [%1], 16;" :: "r"(s), "l"(g));
}
#define CP_COMMIT() asm volatile("cp.async.commit_group;" ::: "memory")
#define CP_WAIT(N)  asm volatile("cp.async.wait_group %0;" :: "n"(N) : "memory")

#define LDSM_X4(r0,r1,r2,r3,addr) \
    asm volatile("ldmatrix.sync.aligned.m8n8.x4.shared.b16 {%0,%1,%2,%3}, [%4];" \
                 : "=r"(r0), "=r"(r1), "=r"(r2), "=r"(r3) : "r"(addr))
#define LDSM_X4T(r0,r1,r2,r3,addr) \
    asm volatile("ldmatrix.sync.aligned.m8n8.x4.trans.shared.b16 {%0,%1,%2,%3}, [%4];" \
                 : "=r"(r0), "=r"(r1), "=r"(r2), "=r"(r3) : "r"(addr))
#define MMA16816(d0,d1,d2,d3,a0,a1,a2,a3,b0,b1) \
    asm volatile("mma.sync.aligned.m16n8k16.row.col.f32.bf16.bf16.f32 " \
                 "{%0,%1,%2,%3}, {%4,%5,%6,%7}, {%8,%9}, {%0,%1,%2,%3};" \
                 : "+f"(d0), "+f"(d1), "+f"(d2), "+f"(d3) \
                 : "r"(a0), "r"(a1), "r"(a2), "r"(a3), "r"(b0), "r"(b1))

// ===========================================================================
// fp32 -> bf16 hi/lo split (single tensor)
// ===========================================================================
__global__ __launch_bounds__(256) void convert_hilo(
    const float* __restrict__ src, __nv_bfloat16* __restrict__ h,
    __nv_bfloat16* __restrict__ l, int n4)
{
    int i = blockIdx.x * blockDim.x + threadIdx.x;
    if (i >= n4) return;
    float4 f = ((const float4*)src)[i];
    uint32_t h01 = packbf(f.y, f.x);
    uint32_t h23 = packbf(f.w, f.z);
    uint32_t l01 = packbf(f.y - hi_f(h01), f.x - lo_f(h01));
    uint32_t l23 = packbf(f.w - hi_f(h23), f.z - lo_f(h23));
    ((uint2*)h)[i] = make_uint2(h01, h23);
    ((uint2*)l)[i] = make_uint2(l01, l23);
}

// all 4 weights in one launch: blockIdx.y selects source, dst offset y*512*512
__global__ __launch_bounds__(256) void convert_w4(
    const float* __restrict__ w0, const float* __restrict__ w1,
    const float* __restrict__ w2, const float* __restrict__ w3,
    __nv_bfloat16* __restrict__ h, __nv_bfloat16* __restrict__ l)
{
    const int n4 = D_MODEL * D_MODEL / 4;
    int i = blockIdx.x * blockDim.x + threadIdx.x;
    if (i >= n4) return;
    int y = blockIdx.y;
    const float* src = (y == 0) ? w0 : (y == 1) ? w1 : (y == 2) ? w2 : w3;
    size_t o = (size_t)y * n4 + i;
    float4 f = ((const float4*)src)[i];
    uint32_t h01 = packbf(f.y, f.x);
    uint32_t h23 = packbf(f.w, f.z);
    uint32_t l01 = packbf(f.y - hi_f(h01), f.x - lo_f(h01));
    uint32_t l23 = packbf(f.w - hi_f(h23), f.z - lo_f(h23));
    ((uint2*)h)[o] = make_uint2(h01, h23);
    ((uint2*)l)[o] = make_uint2(l01, l23);
}

// ===========================================================================
// mma.sync bf16 GEMM, cp.async 2-stage pipeline, optional fused QKV (grid.z).
// out[m,n] = (sum_k A[m,k]*W[n,k] + bias[n]) * alpha ; D = AhWh + AhWl + AlWh.
// CTA 128x128, K-step 32, 256 threads (2x4 warps), warp tile 64x32.
// smem: 2 stages x 4 tiles x (128 rows x 80 B) = 81920 B (dynamic).
// ===========================================================================
#define SROW 80
#define GTILE 10240            // 128*80
#define GSTAGE (4*GTILE)       // 40960

__global__ __launch_bounds__(256) void gemm_mma(
    const __nv_bfloat16* __restrict__ Ah, const __nv_bfloat16* __restrict__ Al,
    const __nv_bfloat16* __restrict__ Whb, const __nv_bfloat16* __restrict__ Wlb,
    const float* __restrict__ b0, const float* __restrict__ b1, const float* __restrict__ b2,
    __nv_bfloat16* __restrict__ oh0, __nv_bfloat16* __restrict__ ol0,
    __nv_bfloat16* __restrict__ oh1, __nv_bfloat16* __restrict__ ol1,
    __nv_bfloat16* __restrict__ oh2, __nv_bfloat16* __restrict__ ol2,
    float* __restrict__ outf, float alphaQ, int wsel)
{
    extern __shared__ __align__(16) char dsm[];
    const uint32_t sb = smem_u32(dsm);

    const int z = blockIdx.z;
    const __nv_bfloat16* Wh = Whb + (size_t)(wsel >= 0 ? wsel : z) * D_MODEL * D_MODEL;
    const __nv_bfloat16* Wl = Wlb + (size_t)(wsel >= 0 ? wsel : z) * D_MODEL * D_MODEL;
    const float* bias = (z == 0) ? b0 : (z == 1) ? b1 : b2;
    __nv_bfloat16* outh = (z == 0) ? oh0 : (z == 1) ? oh1 : oh2;
    __nv_bfloat16* outl = (z == 0) ? ol0 : (z == 1) ? ol1 : ol2;
    const float alpha = (z == 0) ? alphaQ : 1.0f;

    const int tid = threadIdx.x;
    const int wid = tid >> 5, lane = tid & 31;
    const int wm = wid & 1, wn = wid >> 1;
    const int m0 = blockIdx.y * 128;
    const int n0 = blockIdx.x * 128;

    const int lrow = tid >> 1, lseg = tid & 1;
    const uint32_t soff = (uint32_t)lrow * SROW + (uint32_t)lseg * 32;
    const size_t ga_base = (size_t)(m0 + lrow) * D_MODEL + lseg * 16;
    const size_t gw_base = (size_t)(n0 + lrow) * D_MODEL + lseg * 16;

    const uint32_t a_row = (uint32_t)(wm * 64 + (lane & 7) + ((lane >> 3) & 1) * 8);
    const uint32_t a_colb = (uint32_t)((lane >> 4) * 16);
    const uint32_t b_row = (uint32_t)(wn * 32 + (lane & 7) + (lane >> 4) * 8);
    const uint32_t b_colb = (uint32_t)(((lane >> 3) & 1) * 16);

    float d[4][4][4];
    #pragma unroll
    for (int mi = 0; mi < 4; mi++)
        #pragma unroll
        for (int ni = 0; ni < 4; ni++)
            #pragma unroll
            for (int e = 0; e < 4; e++) d[mi][ni][e] = 0.f;

    auto issue = [&](int kc, int st) {
        const int k0 = kc * 32;
        const uint32_t S = sb + (uint32_t)st * GSTAGE;
        cp16(S + 0*GTILE + soff,      Ah + ga_base + k0);
        cp16(S + 0*GTILE + soff + 16, Ah + ga_base + k0 + 8);
        cp16(S + 1*GTILE + soff,      Al + ga_base + k0);
        cp16(S + 1*GTILE + soff + 16, Al + ga_base + k0 + 8);
        cp16(S + 2*GTILE + soff,      Wh + gw_base + k0);
        cp16(S + 2*GTILE + soff + 16, Wh + gw_base + k0 + 8);
        cp16(S + 3*GTILE + soff,      Wl + gw_base + k0);
        cp16(S + 3*GTILE + soff + 16, Wl + gw_base + k0 + 8);
        CP_COMMIT();
    };

    issue(0, 0);
    const int NKC = D_MODEL / 32;   // 16
    for (int kc = 0; kc < NKC; kc++) {
        const int cur = kc & 1;
        __syncthreads();                          // prev compute on cur^1 done
        if (kc + 1 < NKC) { issue(kc + 1, cur ^ 1); CP_WAIT(1); }
        else              { CP_WAIT(0); }
        __syncthreads();                          // stage cur visible

        const uint32_t S = sb + (uint32_t)cur * GSTAGE;
        #pragma unroll
        for (int ks = 0; ks < 2; ks++) {
            const uint32_t kb = (uint32_t)(ks * 32);
            uint32_t ah[4][4], al[4][4];
            #pragma unroll
            for (int mi = 0; mi < 4; mi++) {
                uint32_t addr = (a_row + mi * 16) * SROW + kb + a_colb;
                LDSM_X4(ah[mi][0], ah[mi][1], ah[mi][2], ah[mi][3], S + 0*GTILE + addr);
                LDSM_X4(al[mi][0], al[mi][1], al[mi][2], al[mi][3], S + 1*GTILE + addr);
            }
            uint32_t bh[4][2], bl[4][2];
            #pragma unroll
            for (int nb = 0; nb < 2; nb++) {
                uint32_t addr = (b_row + nb * 16) * SROW + kb + b_colb;
                uint32_t t0, t1, t2, t3;
                LDSM_X4(t0, t1, t2, t3, S + 2*GTILE + addr);
                bh[2*nb][0] = t0; bh[2*nb][1] = t1;
                bh[2*nb+1][0] = t2; bh[2*nb+1][1] = t3;
                LDSM_X4(t0, t1, t2, t3, S + 3*GTILE + addr);
                bl[2*nb][0] = t0; bl[2*nb][1] = t1;
                bl[2*nb+1][0] = t2; bl[2*nb+1][1] = t3;
            }
            #pragma unroll
            for (int mi = 0; mi < 4; mi++)
                #pragma unroll
                for (int ni = 0; ni < 4; ni++) {
                    MMA16816(d[mi][ni][0], d[mi][ni][1], d[mi][ni][2], d[mi][ni][3],
                             ah[mi][0], ah[mi][1], ah[mi][2], ah[mi][3],
                             bh[ni][0], bh[ni][1]);
                    MMA16816(d[mi][ni][0], d[mi][ni][1], d[mi][ni][2], d[mi][ni][3],
                             ah[mi][0], ah[mi][1], ah[mi][2], ah[mi][3],
                             bl[ni][0], bl[ni][1]);
                    MMA16816(d[mi][ni][0], d[mi][ni][1], d[mi][ni][2], d[mi][ni][3],
                             al[mi][0], al[mi][1], al[mi][2], al[mi][3],
                             bh[ni][0], bh[ni][1]);
                }
        }
    }

    #pragma unroll
    for (int mi = 0; mi < 4; mi++) {
        int mrow = m0 + wm * 64 + mi * 16 + (lane >> 2);
        #pragma unroll
        for (int ni = 0; ni < 4; ni++) {
            int ncol = n0 + wn * 32 + ni * 8 + (lane & 3) * 2;
            float bb0 = __ldg(bias + ncol), bb1 = __ldg(bias + ncol + 1);
            float v0 = (d[mi][ni][0] + bb0) * alpha;
            float v1 = (d[mi][ni][1] + bb1) * alpha;
            float v2 = (d[mi][ni][2] + bb0) * alpha;
            float v3 = (d[mi][ni][3] + bb1) * alpha;
            size_t e0 = (size_t)mrow * D_MODEL + ncol;
            size_t e1 = (size_t)(mrow + 8) * D_MODEL + ncol;
            if (outh) {
                uint32_t h01 = packbf(v1, v0);
                uint32_t h23 = packbf(v3, v2);
                uint32_t l01 = packbf(v1 - hi_f(h01), v0 - lo_f(h01));
                uint32_t l23 = packbf(v3 - hi_f(h23), v2 - lo_f(h23));
                ((uint32_t*)outh)[e0 >> 1] = h01;
                ((uint32_t*)outl)[e0 >> 1] = l01;
                ((uint32_t*)outh)[e1 >> 1] = h23;
                ((uint32_t*)outl)[e1 >> 1] = l23;
            } else {
                *(float2*)&outf[e0] = make_float2(v0, v1);
                *(float2*)&outf[e1] = make_float2(v2, v3);
            }
        }
    }
}

// ===========================================================================
// Flash attention on mma.sync with cp.async 2-stage KV pipeline.
// Grid (SEQ/128, B*H), 128 threads (4 warps), warp = 32 q-rows, KV tile 64.
// smem: 2 stages x 4 tiles x (64 rows x 144 B) = 73728 B (dynamic);
// Q hi/lo staged into stage0 region before the pipeline starts.
// ===========================================================================
#define ASTRIDE 72
#define ATILE_B (64*144)       // 9216
#define ASTAGE  (4*ATILE_B)    // 36864

__global__ __launch_bounds__(128) void attn_mma(
    const __nv_bfloat16* __restrict__ Qh, const __nv_bfloat16* __restrict__ Ql,
    const __nv_bfloat16* __restrict__ Kh, const __nv_bfloat16* __restrict__ Kl,
    const __nv_bfloat16* __restrict__ Vh, const __nv_bfloat16* __restrict__ Vl,
    __nv_bfloat16* __restrict__ Oh, __nv_bfloat16* __restrict__ Ol)
{
    extern __shared__ __align__(16) char dsm[];
    __nv_bfloat16* sbuf = (__nv_bfloat16*)dsm;
    const uint32_t sb = smem_u32(dsm);

    const int tid = threadIdx.x;
    const int wid = tid >> 5, lane = tid & 31;
    const int bh = blockIdx.y;
    const int b = bh >> 3, h = bh & 7;
    const int row0 = blockIdx.x * 128;
    const size_t qbase  = ((size_t)(b * SEQ + row0)) * D_MODEL + h * 64;
    const size_t kvbase = ((size_t)(b * SEQ)) * D_MODEL + h * 64;

    // ---- stage Q hi/lo into [0, 36864) and load A-frags ----
    #pragma unroll
    for (int i = 0; i < 8; i++) {
        int lin = tid + i * 128;
        int r = lin >> 3, c = (lin & 7) * 8;
        size_t g = qbase + (size_t)r * D_MODEL + c;
        *(uint4*)&sbuf[r * ASTRIDE + c] = *(const uint4*)&Qh[g];
        *(uint4*)&sbuf[128 * ASTRIDE + r * ASTRIDE + c] = *(const uint4*)&Ql[g];
    }
    __syncthreads();

    uint32_t qfh[2][4][4], qfl[2][4][4];
    {
        uint32_t arow = (uint32_t)(wid * 32 + (lane & 7) + ((lane >> 3) & 1) * 8);
        uint32_t acol = (uint32_t)((lane >> 4) * 16);
        #pragma unroll
        for (int mi = 0; mi < 2; mi++)
            #pragma unroll
            for (int kc = 0; kc < 4; kc++) {
                uint32_t ad = sb + (arow + mi * 16) * 144 + kc * 32 + acol;
                LDSM_X4(qfh[mi][kc][0], qfh[mi][kc][1], qfh[mi][kc][2], qfh[mi][kc][3], ad);
                LDSM_X4(qfl[mi][kc][0], qfl[mi][kc][1], qfl[mi][kc][2], qfl[mi][kc][3],
                        ad + 128 * 144);
            }
    }
    __syncthreads();   // Q region free for pipeline reuse

    float m_[2][2], l_[2][2], o[2][8][4];
    #pragma unroll
    for (int mi = 0; mi < 2; mi++) {
        m_[mi][0] = m_[mi][1] = -3.0e38f;
        l_[mi][0] = l_[mi][1] = 0.f;
        #pragma unroll
        for (int nd = 0; nd < 8; nd++)
            #pragma unroll
            for (int e = 0; e < 4; e++) o[mi][nd][e] = 0.f;
    }

    auto issue = [&](int t, int st) {
        const uint32_t S = sb + (uint32_t)st * ASTAGE;
        #pragma unroll
        for (int i = 0; i < 4; i++) {
            int lin = tid + i * 128;
            int r = lin >> 3, c = (lin & 7) * 8;
            size_t g = kvbase + (size_t)(t * 64 + r) * D_MODEL + c;
            uint32_t so = (uint32_t)(r * 144 + c * 2);
            cp16(S + 0*ATILE_B + so, Kh + g);
            cp16(S + 1*ATILE_B + so, Kl + g);
            cp16(S + 2*ATILE_B + so, Vh + g);
            cp16(S + 3*ATILE_B + so, Vl + g);
        }
        CP_COMMIT();
    };

    issue(0, 0);
    const int NT = SEQ / 64;   // 32
    for (int it = 0; it < NT; it++) {
        const int cur = it & 1;
        __syncthreads();
        if (it + 1 < NT) { issue(it + 1, cur ^ 1); CP_WAIT(1); }
        else             { CP_WAIT(0); }
        __syncthreads();

        const uint32_t S_KH = sb + (uint32_t)cur * ASTAGE;
        const uint32_t S_KL = S_KH + ATILE_B;
        const uint32_t S_VH = S_KH + 2 * ATILE_B;
        const uint32_t S_VL = S_KH + 3 * ATILE_B;

        // ---- S = Q K^T (3-term) ----
        float s[2][8][4];
        #pragma unroll
        for (int mi = 0; mi < 2; mi++)
            #pragma unroll
            for (int ni = 0; ni < 8; ni++)
                #pragma unroll
                for (int e = 0; e < 4; e++) s[mi][ni][e] = 0.f;

        #pragma unroll
        for (int kc = 0; kc < 4; kc++) {
            uint32_t kbh[8][2], kbl[8][2];
            uint32_t brow = (uint32_t)((lane & 7) + (lane >> 4) * 8);
            uint32_t bcol = (uint32_t)(kc * 32 + ((lane >> 3) & 1) * 16);
            #pragma unroll
            for (int nb = 0; nb < 4; nb++) {
                uint32_t ad = (brow + nb * 16) * 144 + bcol;
                uint32_t t0, t1, t2, t3;
                LDSM_X4(t0, t1, t2, t3, S_KH + ad);
                kbh[2*nb][0] = t0; kbh[2*nb][1] = t1;
                kbh[2*nb+1][0] = t2; kbh[2*nb+1][1] = t3;
                LDSM_X4(t0, t1, t2, t3, S_KL + ad);
                kbl[2*nb][0] = t0; kbl[2*nb][1] = t1;
                kbl[2*nb+1][0] = t2; kbl[2*nb+1][1] = t3;
            }
            #pragma unroll
            for (int mi = 0; mi < 2; mi++)
                #pragma unroll
                for (int ni = 0; ni < 8; ni++) {
                    MMA16816(s[mi][ni][0], s[mi][ni][1], s[mi][ni][2], s[mi][ni][3],
                             qfh[mi][kc][0], qfh[mi][kc][1], qfh[mi][kc][2], qfh[mi][kc][3],
                             kbh[ni][0], kbh[ni][1]);
                    MMA16816(s[mi][ni][0], s[mi][ni][1], s[mi][ni][2], s[mi][ni][3],
                             qfh[mi][kc][0], qfh[mi][kc][1], qfh[mi][kc][2], qfh[mi][kc][3],
                             kbl[ni][0], kbl[ni][1]);
                    MMA16816(s[mi][ni][0], s[mi][ni][1], s[mi][ni][2], s[mi][ni][3],
                             qfl[mi][kc][0], qfl[mi][kc][1], qfl[mi][kc][2], qfl[mi][kc][3],
                             kbh[ni][0], kbh[ni][1]);
                }
        }

        // ---- online softmax ----
        uint32_t ph0[2][8], ph1[2][8], pl0[2][8], pl1[2][8];
        #pragma unroll
        for (int mi = 0; mi < 2; mi++) {
            float mx0 = -3.0e38f, mx1 = -3.0e38f;
            #pragma unroll
            for (int ni = 0; ni < 8; ni++) {
                mx0 = fmaxf(mx0, fmaxf(s[mi][ni][0], s[mi][ni][1]));
                mx1 = fmaxf(mx1, fmaxf(s[mi][ni][2], s[mi][ni][3]));
            }
            mx0 = fmaxf(mx0, __shfl_xor_sync(0xffffffffu, mx0, 1));
            mx0 = fmaxf(mx0, __shfl_xor_sync(0xffffffffu, mx0, 2));
            mx1 = fmaxf(mx1, __shfl_xor_sync(0xffffffffu, mx1, 1));
            mx1 = fmaxf(mx1, __shfl_xor_sync(0xffffffffu, mx1, 2));
            float mn0 = fmaxf(m_[mi][0], mx0);
            float mn1 = fmaxf(m_[mi][1], mx1);
            float c0 = fast_ex2(m_[mi][0] - mn0);
            float c1 = fast_ex2(m_[mi][1] - mn1);
            m_[mi][0] = mn0; m_[mi][1] = mn1;
            float s0 = 0.f, s1 = 0.f;
            #pragma unroll
            for (int ni = 0; ni < 8; ni++) {
                float p0 = fast_ex2(s[mi][ni][0] - mn0);
                float p1 = fast_ex2(s[mi][ni][1] - mn0);
                float p2 = fast_ex2(s[mi][ni][2] - mn1);
                float p3 = fast_ex2(s[mi][ni][3] - mn1);
                s0 += p0 + p1; s1 += p2 + p3;
                uint32_t h01 = packbf(p1, p0);
                uint32_t h23 = packbf(p3, p2);
                ph0[mi][ni] = h01; ph1[mi][ni] = h23;
                pl0[mi][ni] = packbf(p1 - hi_f(h01), p0 - lo_f(h01));
                pl1[mi][ni] = packbf(p3 - hi_f(h23), p2 - lo_f(h23));
            }
            s0 += __shfl_xor_sync(0xffffffffu, s0, 1);
            s0 += __shfl_xor_sync(0xffffffffu, s0, 2);
            s1 += __shfl_xor_sync(0xffffffffu, s1, 1);
            s1 += __shfl_xor_sync(0xffffffffu, s1, 2);
            l_[mi][0] = l_[mi][0] * c0 + s0;
            l_[mi][1] = l_[mi][1] * c1 + s1;
            #pragma unroll
            for (int nd = 0; nd < 8; nd++) {
                o[mi][nd][0] *= c0; o[mi][nd][1] *= c0;
                o[mi][nd][2] *= c1; o[mi][nd][3] *= c1;
            }
        }

        // ---- O += P V (3-term) ----
        #pragma unroll
        for (int kt = 0; kt < 4; kt++) {
            uint32_t vbh[8][2], vbl[8][2];
            uint32_t vrow = (uint32_t)(kt * 16 + (lane & 7) + ((lane >> 3) & 1) * 8);
            #pragma unroll
            for (int np = 0; np < 4; np++) {
                uint32_t ad = vrow * 144 + (uint32_t)(np * 32 + (lane >> 4) * 16);
                uint32_t t0, t1, t2, t3;
                LDSM_X4T(t0, t1, t2, t3, S_VH + ad);
                vbh[2*np][0] = t0; vbh[2*np][1] = t1;
                vbh[2*np+1][0] = t2; vbh[2*np+1][1] = t3;
                LDSM_X4T(t0, t1, t2, t3, S_VL + ad);
                vbl[2*np][0] = t0; vbl[2*np][1] = t1;
                vbl[2*np+1][0] = t2; vbl[2*np+1][1] = t3;
            }
            #pragma unroll
            for (int mi = 0; mi < 2; mi++) {
                uint32_t a0 = ph0[mi][2*kt],   a1 = ph1[mi][2*kt];
                uint32_t a2 = ph0[mi][2*kt+1], a3 = ph1[mi][2*kt+1];
                uint32_t r0 = pl0[mi][2*kt],   r1 = pl1[mi][2*kt];
                uint32_t r2 = pl0[mi][2*kt+1], r3 = pl1[mi][2*kt+1];
                #pragma unroll
                for (int nd = 0; nd < 8; nd++) {
                    MMA16816(o[mi][nd][0], o[mi][nd][1], o[mi][nd][2], o[mi][nd][3],
                             a0, a1, a2, a3, vbh[nd][0], vbh[nd][1]);
                    MMA16816(o[mi][nd][0], o[mi][nd][1], o[mi][nd][2], o[mi][nd][3],
                             a0, a1, a2, a3, vbl[nd][0], vbl[nd][1]);
                    MMA16816(o[mi][nd][0], o[mi][nd][1], o[mi][nd][2], o[mi][nd][3],
                             r0, r1, r2, r3, vbh[nd][0], vbh[nd][1]);
                }
            }
        }
    }

    // ---- normalize, split hi/lo, store ----
    #pragma unroll
    for (int mi = 0; mi < 2; mi++)
        #pragma unroll
        for (int hh = 0; hh < 2; hh++) {
            float inv = 1.f / l_[mi][hh];
            int r = row0 + wid * 32 + mi * 16 + (lane >> 2) + hh * 8;
            size_t base = ((size_t)(b * SEQ + r)) * D_MODEL + h * 64 + (lane & 3) * 2;
            #pragma unroll
            for (int nd = 0; nd < 8; nd++) {
                float v0 = o[mi][nd][2*hh]     * inv;
                float v1 = o[mi][nd][2*hh + 1] * inv;
                uint32_t hp = packbf(v1, v0);
                uint32_t lp = packbf(v1 - hi_f(hp), v0 - lo_f(hp));
                size_t e = base + nd * 8;
                ((uint32_t*)Oh)[e >> 1] = hp;
                ((uint32_t*)Ol)[e >> 1] = lp;
            }
        }
}

// ---------------------------------------------------------------------------
extern "C" void kernel_launch(void* const* d_in, const int* in_sizes, int n_in,
                              void* d_out, int out_size)
{
    const float* x  = (const float*)d_in[0];
    const float* Wq = (const float*)d_in[1];
    const float* bq = (const float*)d_in[2];
    const float* Wk = (const float*)d_in[3];
    const float* bk = (const float*)d_in[4];
    const float* Wv = (const float*)d_in[5];
    const float* bv = (const float*)d_in[6];
    const float* Wo = (const float*)d_in[7];
    const float* bo = (const float*)d_in[8];
    float* out = (float*)d_out;

    __nv_bfloat16 *xh, *xl, *qh, *ql, *kh, *kl, *vh, *vl, *wh, *wl;
    cudaGetSymbolAddress((void**)&xh, g_xh);
    cudaGetSymbolAddress((void**)&xl, g_xl);
    cudaGetSymbolAddress((void**)&qh, g_qh);
    cudaGetSymbolAddress((void**)&ql, g_ql);
    cudaGetSymbolAddress((void**)&kh, g_kh);
    cudaGetSymbolAddress((void**)&kl, g_kl);
    cudaGetSymbolAddress((void**)&vh, g_vh);
    cudaGetSymbolAddress((void**)&vl, g_vl);
    cudaGetSymbolAddress((void**)&wh, g_wh);
    cudaGetSymbolAddress((void**)&wl, g_wl);

    const int xn4 = MROWS * D_MODEL / 4;
    const int wn4 = D_MODEL * D_MODEL / 4;

    const int gemm_smem = 2 * GSTAGE;   // 81920
    const int attn_smem = 2 * ASTAGE;   // 73728
    cudaFuncSetAttribute(gemm_mma,
                         cudaFuncAttributeMaxDynamicSharedMemorySize, gemm_smem);
    cudaFuncSetAttribute(attn_mma,
                         cudaFuncAttributeMaxDynamicSharedMemorySize, attn_smem);

    // 1. convert x and all 4 weights (2 launches)
    convert_hilo<<<xn4 / 256, 256>>>(x, xh, xl, xn4);
    convert_w4<<<dim3(wn4 / 256, 4), 256>>>(Wq, Wk, Wv, Wo, wh, wl);

    // 2. fused QKV projection (grid.z selects weight/bias/output)
    gemm_mma<<<dim3(D_MODEL / 128, MROWS / 128, 3), 256, gemm_smem>>>(
        xh, xl, wh, wl, bq, bk, bv,
        qh, ql, kh, kl, vh, vl, nullptr, 0.125f * LOG2E, -1);

    // 3. attention (writes bf16 hi/lo into xh/xl; x is dead)
    attn_mma<<<dim3(SEQ / 128, BATCH * NHEADS), 128, attn_smem>>>(
        qh, ql, kh, kl, vh, vl, xh, xl);

    // 4. output projection (weight slot 3 = Wo), fp32 epilogue to d_out
    gemm_mma<<<dim3(D_MODEL / 128, MROWS / 128, 1), 256, gemm_smem>>>(
        xh, xl, wh, wl, bo, nullptr, nullptr,
        nullptr, nullptr, nullptr, nullptr, nullptr, nullptr, out, 1.0f, 3);
}